// round 2
// baseline (speedup 1.0000x reference)
#include <cuda_runtime.h>
#include <math.h>

// ---------------------------------------------------------------------------
// MotionOptimalTransportLoss — GB300 sm_103a
//
// Levels: c in {64,128,256,512}, N = 1000 (levels 0-2, gathered) / 1024 (level 3).
// Scratch layout: channel-major (c, NPAD=1024) per (tensor, batch, level).
// ---------------------------------------------------------------------------

#define NPAD 1024
#define SCRPB 983040   // floats per (tensor,batch): (64+128+256)*1024 + 512*1024

__device__ float    g_scr[2u * 8u * SCRPB];   // [tensor(x=0/y=1)][batch][level off + ch*NPAD + n]
__device__ float    g_nsq[2 * 32 * 1024];     // squared norms per point: [(t*32+pair)*1024 + n]
__device__ float    g_mu [2 * 32 * 512];      // per-channel means:      [(t*32+pair)*512 + ch]
__device__ unsigned g_rmin[32 * 1024];        // row mins (order-transformed bits)
__device__ unsigned g_cmin[32 * 1024];        // col mins
__device__ float    g_cov[32];                // sum |cov_x - cov_y| per pair

// monotone float <-> uint transform (valid for negatives too)
__device__ __forceinline__ unsigned f2o(float f) {
    unsigned u = __float_as_uint(f);
    return (u & 0x80000000u) ? ~u : (u | 0x80000000u);
}
__device__ __forceinline__ float o2f(unsigned u) {
    return __uint_as_float((u & 0x80000000u) ? (u ^ 0x80000000u) : ~u);
}

// ---------------------------------------------------------------------------
// init: rowmin/colmin = +inf (transformed), covsum = 0
// ---------------------------------------------------------------------------
__global__ void k_init() {
    int i = blockIdx.x * blockDim.x + threadIdx.x;
    if (i < 32 * 1024) { g_rmin[i] = 0xFF800000u; g_cmin[i] = 0xFF800000u; }
    if (i < 32) g_cov[i] = 0.f;
}

// ---------------------------------------------------------------------------
// gather: feat (B,c,hw) -> scratch (c, NPAD) per (tensor,batch); zero padding
// ---------------------------------------------------------------------------
__global__ void k_gather(const float* __restrict__ tgt, const float* __restrict__ gen,
                         const int* __restrict__ idx, int c, int N, int hw, int off) {
    int n  = blockIdx.x * blockDim.x + threadIdx.x;   // 0..1023
    int ch = blockIdx.y;
    int b  = blockIdx.z;
    float vx = 0.f, vy = 0.f;
    if (n < N) {
        int src = idx ? idx[b * 1000 + n] : n;
        size_t base = ((size_t)b * c + ch) * hw + src;
        vx = tgt[base];
        vy = gen[base];
    }
    size_t d = (size_t)b * SCRPB + off + (size_t)ch * NPAD + n;
    g_scr[d] = vx;
    g_scr[(size_t)8 * SCRPB + d] = vy;
}

// ---------------------------------------------------------------------------
// norms: per point squared L2 norm over channels (coalesced over n)
// ---------------------------------------------------------------------------
__global__ void k_norms(int c, int off, int lv) {
    int n = threadIdx.x;          // block 1024
    int b = blockIdx.x;           // 0..7
    int t = blockIdx.y;           // 0..1
    const float* base = g_scr + ((size_t)t * 8 + b) * SCRPB + off;
    float acc = 0.f;
    for (int k = 0; k < c; k++) { float v = base[(size_t)k * NPAD + n]; acc += v * v; }
    g_nsq[(t * 32 + b * 4 + lv) * 1024 + n] = acc;
}

// ---------------------------------------------------------------------------
// means: one warp per channel (coalesced over n)
// ---------------------------------------------------------------------------
__global__ void k_means(int c, int N, int off, int lv) {
    int w = threadIdx.x >> 5, lane = threadIdx.x & 31;
    int ch = blockIdx.x * 8 + w;
    if (ch >= c) return;
    int b = blockIdx.y, t = blockIdx.z;
    const float* row = g_scr + ((size_t)t * 8 + b) * SCRPB + off + (size_t)ch * NPAD;
    float s = 0.f;
    for (int n = lane; n < NPAD; n += 32) s += row[n];
#pragma unroll
    for (int o = 16; o; o >>= 1) s += __shfl_xor_sync(0xFFFFFFFFu, s, o);
    if (lane == 0) g_mu[(t * 32 + b * 4 + lv) * 512 + ch] = s / (float)N;
}

// ---------------------------------------------------------------------------
// style: fused  D = 1 - (X Y^T)/(|x|+eps)/(|y|+eps)  with row/col min epilogue.
// 128x128 block tile, 8x8 microtile (split 64+64 for conflict-free LDS.128).
// ---------------------------------------------------------------------------
__global__ void __launch_bounds__(256)
k_style(int c, int N, int off, int lv) {
    __shared__ float As[16][128];
    __shared__ float Bs[16][128];
    __shared__ unsigned rm[128], cm[128];

    int b  = blockIdx.z;
    int i0 = blockIdx.y * 128, j0 = blockIdx.x * 128;
    int tx = threadIdx.x, ty = threadIdx.y;       // 16x16
    int tid = ty * 16 + tx;
    const float* X = g_scr + (size_t)b * SCRPB + off;
    const float* Y = g_scr + (size_t)(8 + b) * SCRPB + off;

    float acc[8][8];
#pragma unroll
    for (int r = 0; r < 8; r++)
#pragma unroll
        for (int s = 0; s < 8; s++) acc[r][s] = 0.f;

    for (int k0 = 0; k0 < c; k0 += 16) {
#pragma unroll
        for (int r = 0; r < 8; r++) {
            int e = tid + r * 256;            // 0..2047
            int kk = e >> 7, col = e & 127;
            As[kk][col] = X[(size_t)(k0 + kk) * NPAD + i0 + col];
            Bs[kk][col] = Y[(size_t)(k0 + kk) * NPAD + j0 + col];
        }
        __syncthreads();
#pragma unroll
        for (int k = 0; k < 16; k++) {
            float a[8], bb[8];
            *(float4*)&a[0]  = *(const float4*)&As[k][ty * 4];
            *(float4*)&a[4]  = *(const float4*)&As[k][64 + ty * 4];
            *(float4*)&bb[0] = *(const float4*)&Bs[k][tx * 4];
            *(float4*)&bb[4] = *(const float4*)&Bs[k][64 + tx * 4];
#pragma unroll
            for (int r = 0; r < 8; r++)
#pragma unroll
                for (int s = 0; s < 8; s++) acc[r][s] = fmaf(a[r], bb[s], acc[r][s]);
        }
        __syncthreads();
    }

    // local row/col index (split microtile): r<4 -> ty*4+r ; r>=4 -> 64+ty*4+(r-4)
    int lr[8], lc[8];
#pragma unroll
    for (int r = 0; r < 8; r++) {
        lr[r] = (r < 4) ? (ty * 4 + r) : (64 + ty * 4 + (r - 4));
        lc[r] = (r < 4) ? (tx * 4 + r) : (64 + tx * 4 + (r - 4));
    }

    int pair = b * 4 + lv;
    float invx[8], invy[8];
    bool vi[8], vj[8];
#pragma unroll
    for (int r = 0; r < 8; r++) {
        int i = i0 + lr[r];
        vi[r] = (i < N);
        invx[r] = 1.f / (sqrtf(g_nsq[pair * 1024 + i]) + 1e-10f);
        int j = j0 + lc[r];
        vj[r] = (j < N);
        invy[r] = 1.f / (sqrtf(g_nsq[(32 + pair) * 1024 + j]) + 1e-10f);
    }

    float rmin[8], cmin[8];
#pragma unroll
    for (int r = 0; r < 8; r++) { rmin[r] = INFINITY; cmin[r] = INFINITY; }
#pragma unroll
    for (int r = 0; r < 8; r++)
#pragma unroll
        for (int s = 0; s < 8; s++)
            if (vi[r] && vj[s]) {
                float d = 1.f - acc[r][s] * invx[r] * invy[s];
                rmin[r] = fminf(rmin[r], d);
                cmin[s] = fminf(cmin[s], d);
            }

    if (tid < 128) { rm[tid] = 0xFF800000u; cm[tid] = 0xFF800000u; }
    __syncthreads();
#pragma unroll
    for (int r = 0; r < 8; r++) {
        if (vi[r]) atomicMin(&rm[lr[r]], f2o(rmin[r]));
        if (vj[r]) atomicMin(&cm[lc[r]], f2o(cmin[r]));
    }
    __syncthreads();
    if (tid < 128) {
        int i = i0 + tid; if (i < N) atomicMin(&g_rmin[pair * 1024 + i], rm[tid]);
        int j = j0 + tid; if (j < N) atomicMin(&g_cmin[pair * 1024 + j], cm[tid]);
    }
}

// ---------------------------------------------------------------------------
// cov: sum |X_cov - Y_cov| per pair. Computes S = X^T X - Y^T Y tile-wise
// (upper triangle of 64x64 channel tiles only), mean-corrects in epilogue.
// ---------------------------------------------------------------------------
__global__ void __launch_bounds__(256)
k_cov(int c, int N, int off, int lv, int T) {
    __shared__ float Xa_s[64][33], Xb_s[64][33], Ya_s[64][33], Yb_s[64][33];
    __shared__ float red[256];

    // linear -> upper triangle (ta, tb>=ta)
    int lin = blockIdx.x, ta = 0, rem = lin;
    while (rem >= T - ta) { rem -= (T - ta); ta++; }
    int tb = ta + rem;

    int b = blockIdx.y;
    int tx = threadIdx.x, ty = threadIdx.y;
    int tid = ty * 16 + tx;
    int cha0 = ta * 64, chb0 = tb * 64;
    const float* X = g_scr + (size_t)b * SCRPB + off;
    const float* Y = g_scr + (size_t)(8 + b) * SCRPB + off;

    float acc[4][4];
#pragma unroll
    for (int r = 0; r < 4; r++)
#pragma unroll
        for (int s = 0; s < 4; s++) acc[r][s] = 0.f;

    for (int n0 = 0; n0 < NPAD; n0 += 32) {
#pragma unroll
        for (int r = 0; r < 8; r++) {
            int e = tid + r * 256;          // 0..2047
            int ch = e >> 5, n = e & 31;
            Xa_s[ch][n] = X[(size_t)(cha0 + ch) * NPAD + n0 + n];
            Xb_s[ch][n] = X[(size_t)(chb0 + ch) * NPAD + n0 + n];
            Ya_s[ch][n] = Y[(size_t)(cha0 + ch) * NPAD + n0 + n];
            Yb_s[ch][n] = Y[(size_t)(chb0 + ch) * NPAD + n0 + n];
        }
        __syncthreads();
#pragma unroll 8
        for (int n = 0; n < 32; n++) {
            float xa[4], xb[4], ya[4], yb[4];
#pragma unroll
            for (int r = 0; r < 4; r++) {
                xa[r] = Xa_s[ty * 4 + r][n];
                ya[r] = Ya_s[ty * 4 + r][n];
                xb[r] = Xb_s[tx * 4 + r][n];
                yb[r] = Yb_s[tx * 4 + r][n];
            }
#pragma unroll
            for (int r = 0; r < 4; r++)
#pragma unroll
                for (int s = 0; s < 4; s++) {
                    acc[r][s] = fmaf(xa[r], xb[s], acc[r][s]);
                    acc[r][s] = fmaf(-ya[r], yb[s], acc[r][s]);
                }
        }
        __syncthreads();
    }

    int pair = b * 4 + lv;
    const float* mux = g_mu + pair * 512;
    const float* muy = g_mu + (32 + pair) * 512;
    float Nf = (float)N, inv_nm1 = 1.f / (Nf - 1.f);
    float local = 0.f;
#pragma unroll
    for (int r = 0; r < 4; r++) {
        int a = cha0 + ty * 4 + r;
        float mxa = mux[a], mya = muy[a];
#pragma unroll
        for (int s = 0; s < 4; s++) {
            int bc = chb0 + tx * 4 + s;
            float cd = (acc[r][s] - Nf * (mxa * mux[bc] - mya * muy[bc])) * inv_nm1;
            float w = (ta == tb) ? ((bc > a) ? 2.f : (bc == a ? 1.f : 0.f)) : 2.f;
            local += w * fabsf(cd);
        }
    }

    red[tid] = local;
    __syncthreads();
    for (int o = 128; o; o >>= 1) {
        if (tid < o) red[tid] += red[tid + o];
        __syncthreads();
    }
    if (tid == 0) atomicAdd(&g_cov[pair], red[0]);
}

// ---------------------------------------------------------------------------
// finalize: per-pair loss = max(mean rowmin, mean colmin) + mean|mu_d| + mean|cov_d|
// out = (sum over pairs) / B
// ---------------------------------------------------------------------------
__device__ float blk_reduce1024(float v, float* sm) {
    int lane = threadIdx.x & 31, w = threadIdx.x >> 5;
#pragma unroll
    for (int o = 16; o; o >>= 1) v += __shfl_xor_sync(0xFFFFFFFFu, v, o);
    if (lane == 0) sm[w] = v;
    __syncthreads();
    float r = 0.f;
    if (w == 0) {
        r = sm[lane];
#pragma unroll
        for (int o = 16; o; o >>= 1) r += __shfl_xor_sync(0xFFFFFFFFu, r, o);
    }
    __syncthreads();
    return r;   // valid in warp 0
}

__global__ void k_final(float* __restrict__ out) {
    __shared__ float sm[32];
    const int cs[4] = {64, 128, 256, 512};
    float total = 0.f;
    int tid = threadIdx.x;
    for (int pair = 0; pair < 32; pair++) {
        int lv = pair & 3;
        int c = cs[lv], N = (lv == 3) ? 1024 : 1000;
        float v1 = 0.f, v2 = 0.f, v3 = 0.f;
        if (tid < N) {
            v1 = o2f(g_rmin[pair * 1024 + tid]);
            v2 = o2f(g_cmin[pair * 1024 + tid]);
        }
        if (tid < c) v3 = fabsf(g_mu[pair * 512 + tid] - g_mu[(32 + pair) * 512 + tid]);
        float s1 = blk_reduce1024(v1, sm);
        float s2 = blk_reduce1024(v2, sm);
        float s3 = blk_reduce1024(v3, sm);
        if (tid == 0) {
            float style = fmaxf(s1 / (float)N, s2 / (float)N);
            float mud   = s3 / (float)c;
            float cov   = g_cov[pair] / ((float)c * (float)c);
            total += style + mud + cov;
        }
    }
    if (tid == 0) out[0] = total / 8.f;
}

// ---------------------------------------------------------------------------
// launch — inputs classified by ELEMENT COUNT (robust to metadata ordering).
// setup_inputs() interleaves: target_feat0, gen_feat0, target_feat1, gen_feat1,
// ..., idx0, idx1, idx2. Within each unique size, target precedes gen and
// idx buffers appear in level order.
// ---------------------------------------------------------------------------
extern "C" void kernel_launch(void* const* d_in, const int* in_sizes, int n_in,
                              void* d_out, int out_size) {
    const float* tf[4] = {0, 0, 0, 0};
    const float* gf[4] = {0, 0, 0, 0};
    const int*   ix[3] = {0, 0, 0};

    const long long LSZ[4] = {8LL * 64 * 256 * 256, 8LL * 128 * 128 * 128,
                              8LL * 256 * 64 * 64,  8LL * 512 * 32 * 32};
    int n_idx = 0;
    for (int i = 0; i < n_in; i++) {
        long long sz = in_sizes[i];
        if (sz == 8LL * 1000) {
            if (n_idx < 3) ix[n_idx++] = (const int*)d_in[i];
            continue;
        }
        for (int lv = 0; lv < 4; lv++) {
            if (sz == LSZ[lv]) {
                if (!tf[lv]) tf[lv] = (const float*)d_in[i];
                else if (!gf[lv]) gf[lv] = (const float*)d_in[i];
                break;
            }
        }
    }
    float* out = (float*)d_out;

    const int C[4]   = {64, 128, 256, 512};
    const int N_[4]  = {1000, 1000, 1000, 1024};
    const int HW[4]  = {65536, 16384, 4096, 1024};
    const int OFF[4] = {0, 65536, 196608, 458752};
    const int TRI[4] = {1, 3, 10, 36};   // T*(T+1)/2, T = c/64

    k_init<<<128, 256>>>();

    for (int lv = 0; lv < 4; lv++)
        k_gather<<<dim3(4, C[lv], 8), 256>>>(tf[lv], gf[lv], lv < 3 ? ix[lv] : nullptr,
                                             C[lv], N_[lv], HW[lv], OFF[lv]);
    for (int lv = 0; lv < 4; lv++)
        k_norms<<<dim3(8, 2), 1024>>>(C[lv], OFF[lv], lv);
    for (int lv = 0; lv < 4; lv++)
        k_means<<<dim3(C[lv] / 8, 8, 2), 256>>>(C[lv], N_[lv], OFF[lv], lv);
    for (int lv = 0; lv < 4; lv++)
        k_style<<<dim3(8, 8, 8), dim3(16, 16)>>>(C[lv], N_[lv], OFF[lv], lv);
    for (int lv = 0; lv < 4; lv++)
        k_cov<<<dim3(TRI[lv], 8), dim3(16, 16)>>>(C[lv], N_[lv], OFF[lv], lv, C[lv] / 64);

    k_final<<<1, 1024>>>(out);
}

// round 3
// speedup vs baseline: 2.1165x; 2.1165x over previous
#include <cuda_runtime.h>
#include <math.h>

// ---------------------------------------------------------------------------
// MotionOptimalTransportLoss — GB300 sm_103a, tf32 mma.sync version
// Levels: c in {64,128,256,512}, N = 1000 (lv 0-2) / 1024 (lv 3), NPAD=1024.
// Scratch: channel-major fp32 (c, NPAD) per (tensor, batch, level).
// ---------------------------------------------------------------------------

#define NPAD 1024
#define SCRPB 983040   // (64+128+256+512)*1024

__device__ float    g_scr[2u * 8u * SCRPB];
__device__ float    g_nsq[2 * 32 * 1024];
__device__ float    g_mu [2 * 32 * 512];
__device__ unsigned g_rmin[32 * 1024];
__device__ unsigned g_cmin[32 * 1024];
__device__ float    g_cov[32];
__device__ float    g_pl[32];

__device__ __forceinline__ unsigned f2o(float f) {
    unsigned u = __float_as_uint(f);
    return (u & 0x80000000u) ? ~u : (u | 0x80000000u);
}
__device__ __forceinline__ float o2f(unsigned u) {
    return __uint_as_float((u & 0x80000000u) ? (u ^ 0x80000000u) : ~u);
}
__device__ __forceinline__ float tf32r(float x) {
    float r; asm("cvt.rna.tf32.f32 %0, %1;" : "=f"(r) : "f"(x)); return r;
}
__device__ __forceinline__ void mma8(float* d, const unsigned* a, const unsigned* b) {
    asm volatile(
        "mma.sync.aligned.m16n8k8.row.col.f32.tf32.tf32.f32 "
        "{%0,%1,%2,%3}, {%4,%5,%6,%7}, {%8,%9}, {%0,%1,%2,%3};\n"
        : "+f"(d[0]), "+f"(d[1]), "+f"(d[2]), "+f"(d[3])
        : "r"(a[0]), "r"(a[1]), "r"(a[2]), "r"(a[3]), "r"(b[0]), "r"(b[1]));
}

// ---------------------------------------------------------------------------
__global__ void k_init() {
    int i = blockIdx.x * blockDim.x + threadIdx.x;
    if (i < 65536) g_nsq[i] = 0.f;
    if (i < 32768) { g_rmin[i] = 0xFF800000u; g_cmin[i] = 0xFF800000u; }
    if (i < 32) g_cov[i] = 0.f;
}

// ---------------------------------------------------------------------------
__global__ void k_gather(const float* __restrict__ tgt, const float* __restrict__ gen,
                         const int* __restrict__ idx, int c, int N, int hw, int off) {
    int n  = blockIdx.x * blockDim.x + threadIdx.x;
    int ch = blockIdx.y;
    int b  = blockIdx.z;
    float vx = 0.f, vy = 0.f;
    if (n < N) {
        int src = idx ? idx[b * 1000 + n] : n;
        size_t base = ((size_t)b * c + ch) * hw + src;
        vx = tgt[base];
        vy = gen[base];
    }
    size_t d = (size_t)b * SCRPB + off + (size_t)ch * NPAD + n;
    g_scr[d] = vx;
    g_scr[(size_t)8 * SCRPB + d] = vy;
}

// ---------------------------------------------------------------------------
// norms: partial over 64-channel slabs, atomicAdd into g_nsq (zero-inited)
// ---------------------------------------------------------------------------
__global__ void k_norms(int c, int off, int lv) {
    int n = threadIdx.x;
    int b = blockIdx.x, t = blockIdx.y;
    int cs = blockIdx.z * 64;
    const float* base = g_scr + ((size_t)t * 8 + b) * SCRPB + off + (size_t)cs * NPAD;
    float acc = 0.f;
#pragma unroll 8
    for (int k = 0; k < 64; k++) { float v = base[(size_t)k * NPAD + n]; acc += v * v; }
    atomicAdd(&g_nsq[(t * 32 + b * 4 + lv) * 1024 + n], acc);
}

// ---------------------------------------------------------------------------
__global__ void k_means(int c, int N, int off, int lv) {
    int w = threadIdx.x >> 5, lane = threadIdx.x & 31;
    int ch = blockIdx.x * 8 + w;
    if (ch >= c) return;
    int b = blockIdx.y, t = blockIdx.z;
    const float* row = g_scr + ((size_t)t * 8 + b) * SCRPB + off + (size_t)ch * NPAD;
    float s = 0.f;
    for (int n = lane; n < NPAD; n += 32) s += row[n];
#pragma unroll
    for (int o = 16; o; o >>= 1) s += __shfl_xor_sync(0xFFFFFFFFu, s, o);
    if (lane == 0) g_mu[(t * 32 + b * 4 + lv) * 512 + ch] = s / (float)N;
}

// ---------------------------------------------------------------------------
// style: D = 1 - (X^T Y)/(|x|+eps)/(|y|+eps), fused row/col min, tf32 mma.
// CTA: 128x128 tile, 256 thr (8 warps of 64x32). smem [k][m], stride 136.
// ---------------------------------------------------------------------------
#define SA 136
__global__ void __launch_bounds__(256, 2)
k_style(int c, int N, int off, int lv) {
    __shared__ float As[32 * SA];
    __shared__ float Bs[32 * SA];
    __shared__ unsigned rm[128], cm[128];

    int b  = blockIdx.z;
    int i0 = blockIdx.y * 128, j0 = blockIdx.x * 128;
    int tid = threadIdx.x, wid = tid >> 5, lane = tid & 31;
    int g = lane >> 2, t = lane & 3;
    int wm = (wid >> 2) * 64, wn = (wid & 3) * 32;
    const float* X = g_scr + (size_t)b * SCRPB + off;
    const float* Y = g_scr + (size_t)(8 + b) * SCRPB + off;

    if (tid < 128) { rm[tid] = 0xFF800000u; cm[tid] = 0xFF800000u; }

    float acc[4][4][4];
#pragma unroll
    for (int mt = 0; mt < 4; mt++)
#pragma unroll
        for (int nt = 0; nt < 4; nt++)
#pragma unroll
            for (int r = 0; r < 4; r++) acc[mt][nt][r] = 0.f;

    int lch = tid >> 3, lq = tid & 7;   // 32 ch rows x 8 loaders
    for (int k0 = 0; k0 < c; k0 += 32) {
        __syncthreads();
#pragma unroll
        for (int j = 0; j < 4; j++) {
            int col = lq * 16 + j * 4;
            float4 va = *(const float4*)&X[(size_t)(k0 + lch) * NPAD + i0 + col];
            float4 vb = *(const float4*)&Y[(size_t)(k0 + lch) * NPAD + j0 + col];
            va.x = tf32r(va.x); va.y = tf32r(va.y); va.z = tf32r(va.z); va.w = tf32r(va.w);
            vb.x = tf32r(vb.x); vb.y = tf32r(vb.y); vb.z = tf32r(vb.z); vb.w = tf32r(vb.w);
            *(float4*)&As[lch * SA + col] = va;
            *(float4*)&Bs[lch * SA + col] = vb;
        }
        __syncthreads();
#pragma unroll
        for (int k8 = 0; k8 < 4; k8++) {
            int kb = k8 * 8;
            unsigned a[4][4], bb[4][2];
#pragma unroll
            for (int mt = 0; mt < 4; mt++) {
                int r = wm + mt * 16 + g;
                a[mt][0] = __float_as_uint(As[(kb + t) * SA + r]);
                a[mt][1] = __float_as_uint(As[(kb + t) * SA + r + 8]);
                a[mt][2] = __float_as_uint(As[(kb + t + 4) * SA + r]);
                a[mt][3] = __float_as_uint(As[(kb + t + 4) * SA + r + 8]);
            }
#pragma unroll
            for (int nt = 0; nt < 4; nt++) {
                int cc = wn + nt * 8 + g;
                bb[nt][0] = __float_as_uint(Bs[(kb + t) * SA + cc]);
                bb[nt][1] = __float_as_uint(Bs[(kb + t + 4) * SA + cc]);
            }
#pragma unroll
            for (int mt = 0; mt < 4; mt++)
#pragma unroll
                for (int nt = 0; nt < 4; nt++) mma8(acc[mt][nt], a[mt], bb[nt]);
        }
    }

    // epilogue
    int pair = b * 4 + lv;
    const float* nsqX = g_nsq + pair * 1024;
    const float* nsqY = g_nsq + (32 + pair) * 1024;
    float invx[4][2], invy[4][2];
    bool vi[4][2], vj[4][2];
#pragma unroll
    for (int mt = 0; mt < 4; mt++)
#pragma unroll
        for (int h = 0; h < 2; h++) {
            int i = i0 + wm + mt * 16 + g + h * 8;
            vi[mt][h] = (i < N);
            invx[mt][h] = 1.f / (sqrtf(nsqX[i]) + 1e-10f);
        }
#pragma unroll
    for (int nt = 0; nt < 4; nt++)
#pragma unroll
        for (int u = 0; u < 2; u++) {
            int j = j0 + wn + nt * 8 + 2 * t + u;
            vj[nt][u] = (j < N);
            invy[nt][u] = 1.f / (sqrtf(nsqY[j]) + 1e-10f);
        }

    float rmin[4][2], cmin[4][2];
#pragma unroll
    for (int a1 = 0; a1 < 4; a1++)
#pragma unroll
        for (int a2 = 0; a2 < 2; a2++) { rmin[a1][a2] = INFINITY; cmin[a1][a2] = INFINITY; }

#pragma unroll
    for (int mt = 0; mt < 4; mt++)
#pragma unroll
        for (int nt = 0; nt < 4; nt++)
#pragma unroll
            for (int h = 0; h < 2; h++)
#pragma unroll
                for (int u = 0; u < 2; u++) {
                    float d = 1.f - acc[mt][nt][h * 2 + u] * invx[mt][h] * invy[nt][u];
                    float dr = vj[nt][u] ? d : INFINITY;
                    rmin[mt][h] = fminf(rmin[mt][h], dr);
                    float dc = vi[mt][h] ? d : INFINITY;
                    cmin[nt][u] = fminf(cmin[nt][u], dc);
                }

    // reduce rmin over t (lanes xor 1,2); cmin over g (xor 4,8,16)
#pragma unroll
    for (int mt = 0; mt < 4; mt++)
#pragma unroll
        for (int h = 0; h < 2; h++) {
            float v = rmin[mt][h];
            v = fminf(v, __shfl_xor_sync(0xFFFFFFFFu, v, 1));
            v = fminf(v, __shfl_xor_sync(0xFFFFFFFFu, v, 2));
            rmin[mt][h] = v;
        }
#pragma unroll
    for (int nt = 0; nt < 4; nt++)
#pragma unroll
        for (int u = 0; u < 2; u++) {
            float v = cmin[nt][u];
            v = fminf(v, __shfl_xor_sync(0xFFFFFFFFu, v, 4));
            v = fminf(v, __shfl_xor_sync(0xFFFFFFFFu, v, 8));
            v = fminf(v, __shfl_xor_sync(0xFFFFFFFFu, v, 16));
            cmin[nt][u] = v;
        }
    if (t == 0) {
#pragma unroll
        for (int mt = 0; mt < 4; mt++)
#pragma unroll
            for (int h = 0; h < 2; h++)
                atomicMin(&rm[wm + mt * 16 + g + h * 8], f2o(rmin[mt][h]));
    }
    if (g == 0) {
#pragma unroll
        for (int nt = 0; nt < 4; nt++)
#pragma unroll
            for (int u = 0; u < 2; u++)
                atomicMin(&cm[wn + nt * 8 + 2 * t + u], f2o(cmin[nt][u]));
    }
    __syncthreads();
    if (tid < 128) {
        int i = i0 + tid; if (i < N) atomicMin(&g_rmin[pair * 1024 + i], rm[tid]);
        int j = j0 + tid; if (j < N) atomicMin(&g_cmin[pair * 1024 + j], cm[tid]);
    }
}

// ---------------------------------------------------------------------------
// cov: sum |X_cov - Y_cov| per pair via tf32 mma. CTA: 64x64 channel tile,
// 8 warps of 32x16. Single accumulator: pass0 A=X,B=X; pass1 A=-Y,B=Y.
// smem A[m][k] / B[n][k], stride 68, kc=64.
// ---------------------------------------------------------------------------
#define SC 68
__global__ void __launch_bounds__(256, 2)
k_cov(int c, int N, int off, int lv, int T) {
    __shared__ float As[64 * SC];
    __shared__ float Bs[64 * SC];
    __shared__ float red[256];

    int lin = blockIdx.x, ta = 0, rem = lin;
    while (rem >= T - ta) { rem -= (T - ta); ta++; }
    int tb = ta + rem;

    int b = blockIdx.y;
    int tid = threadIdx.x, wid = tid >> 5, lane = tid & 31;
    int g = lane >> 2, t = lane & 3;
    int wm = (wid >> 2) * 32, wn = (wid & 3) * 16;
    int cha0 = ta * 64, chb0 = tb * 64;
    const float* X = g_scr + (size_t)b * SCRPB + off;
    const float* Y = g_scr + (size_t)(8 + b) * SCRPB + off;

    float acc[2][2][4];
#pragma unroll
    for (int mt = 0; mt < 2; mt++)
#pragma unroll
        for (int nt = 0; nt < 2; nt++)
#pragma unroll
            for (int r = 0; r < 4; r++) acc[mt][nt][r] = 0.f;

    int lch = tid >> 2, lq = tid & 3;   // 64 rows x 4 loaders
    for (int p = 0; p < 2; p++) {
        const float* src = p ? Y : X;
        float sgn = p ? -1.f : 1.f;
        for (int n0 = 0; n0 < NPAD; n0 += 64) {
            __syncthreads();
#pragma unroll
            for (int j = 0; j < 4; j++) {
                int col = lq * 16 + j * 4;
                float4 va = *(const float4*)&src[(size_t)(cha0 + lch) * NPAD + n0 + col];
                float4 vb = *(const float4*)&src[(size_t)(chb0 + lch) * NPAD + n0 + col];
                va.x = tf32r(sgn * va.x); va.y = tf32r(sgn * va.y);
                va.z = tf32r(sgn * va.z); va.w = tf32r(sgn * va.w);
                vb.x = tf32r(vb.x); vb.y = tf32r(vb.y); vb.z = tf32r(vb.z); vb.w = tf32r(vb.w);
                *(float4*)&As[lch * SC + col] = va;
                *(float4*)&Bs[lch * SC + col] = vb;
            }
            __syncthreads();
#pragma unroll
            for (int k8 = 0; k8 < 8; k8++) {
                int kb = k8 * 8;
                unsigned a[2][4], bb[2][2];
#pragma unroll
                for (int mt = 0; mt < 2; mt++) {
                    int r = wm + mt * 16 + g;
                    a[mt][0] = __float_as_uint(As[r * SC + kb + t]);
                    a[mt][1] = __float_as_uint(As[(r + 8) * SC + kb + t]);
                    a[mt][2] = __float_as_uint(As[r * SC + kb + t + 4]);
                    a[mt][3] = __float_as_uint(As[(r + 8) * SC + kb + t + 4]);
                }
#pragma unroll
                for (int nt = 0; nt < 2; nt++) {
                    int cc = wn + nt * 8 + g;
                    bb[nt][0] = __float_as_uint(Bs[cc * SC + kb + t]);
                    bb[nt][1] = __float_as_uint(Bs[cc * SC + kb + t + 4]);
                }
#pragma unroll
                for (int mt = 0; mt < 2; mt++)
#pragma unroll
                    for (int nt = 0; nt < 2; nt++) mma8(acc[mt][nt], a[mt], bb[nt]);
            }
        }
    }

    int pair = b * 4 + lv;
    const float* mux = g_mu + pair * 512;
    const float* muy = g_mu + (32 + pair) * 512;
    float Nf = (float)N, inv_nm1 = 1.f / (Nf - 1.f);
    float local = 0.f;
#pragma unroll
    for (int mt = 0; mt < 2; mt++)
#pragma unroll
        for (int h = 0; h < 2; h++) {
            int row = cha0 + wm + mt * 16 + g + h * 8;
            float mxa = mux[row], mya = muy[row];
#pragma unroll
            for (int nt = 0; nt < 2; nt++)
#pragma unroll
                for (int u = 0; u < 2; u++) {
                    int col = chb0 + wn + nt * 8 + 2 * t + u;
                    float cd = (acc[mt][nt][h * 2 + u]
                                - Nf * (mxa * mux[col] - mya * muy[col])) * inv_nm1;
                    float w = (ta == tb) ? ((col > row) ? 2.f : (col == row ? 1.f : 0.f)) : 2.f;
                    local += w * fabsf(cd);
                }
        }

    red[tid] = local;
    __syncthreads();
    for (int o = 128; o; o >>= 1) {
        if (tid < o) red[tid] += red[tid + o];
        __syncthreads();
    }
    if (tid == 0) atomicAdd(&g_cov[pair], red[0]);
}

// ---------------------------------------------------------------------------
__device__ float blk_reduce1024(float v, float* sm) {
    int lane = threadIdx.x & 31, w = threadIdx.x >> 5;
#pragma unroll
    for (int o = 16; o; o >>= 1) v += __shfl_xor_sync(0xFFFFFFFFu, v, o);
    if (lane == 0) sm[w] = v;
    __syncthreads();
    float r = 0.f;
    if (w == 0) {
        r = sm[lane];
#pragma unroll
        for (int o = 16; o; o >>= 1) r += __shfl_xor_sync(0xFFFFFFFFu, r, o);
    }
    __syncthreads();
    return r;
}

__global__ void k_pairloss() {
    __shared__ float sm[32];
    const int cs[4] = {64, 128, 256, 512};
    int pair = blockIdx.x;
    int lv = pair & 3;
    int c = cs[lv], N = (lv == 3) ? 1024 : 1000;
    int tid = threadIdx.x;
    float v1 = 0.f, v2 = 0.f, v3 = 0.f;
    if (tid < N) {
        v1 = o2f(g_rmin[pair * 1024 + tid]);
        v2 = o2f(g_cmin[pair * 1024 + tid]);
    }
    if (tid < c) v3 = fabsf(g_mu[pair * 512 + tid] - g_mu[(32 + pair) * 512 + tid]);
    float s1 = blk_reduce1024(v1, sm);
    float s2 = blk_reduce1024(v2, sm);
    float s3 = blk_reduce1024(v3, sm);
    if (tid == 0) {
        float style = fmaxf(s1 / (float)N, s2 / (float)N);
        float mud   = s3 / (float)c;
        float cov   = g_cov[pair] / ((float)c * (float)c);
        g_pl[pair] = style + mud + cov;
    }
}

__global__ void k_out(float* __restrict__ out) {
    float v = g_pl[threadIdx.x];
#pragma unroll
    for (int o = 16; o; o >>= 1) v += __shfl_xor_sync(0xFFFFFFFFu, v, o);
    if (threadIdx.x == 0) out[0] = v / 8.f;
}

// ---------------------------------------------------------------------------
extern "C" void kernel_launch(void* const* d_in, const int* in_sizes, int n_in,
                              void* d_out, int out_size) {
    const float* tf[4] = {0, 0, 0, 0};
    const float* gf[4] = {0, 0, 0, 0};
    const int*   ix[3] = {0, 0, 0};

    const long long LSZ[4] = {8LL * 64 * 256 * 256, 8LL * 128 * 128 * 128,
                              8LL * 256 * 64 * 64,  8LL * 512 * 32 * 32};
    int n_idx = 0;
    for (int i = 0; i < n_in; i++) {
        long long sz = in_sizes[i];
        if (sz == 8LL * 1000) {
            if (n_idx < 3) ix[n_idx++] = (const int*)d_in[i];
            continue;
        }
        for (int lv = 0; lv < 4; lv++) {
            if (sz == LSZ[lv]) {
                if (!tf[lv]) tf[lv] = (const float*)d_in[i];
                else if (!gf[lv]) gf[lv] = (const float*)d_in[i];
                break;
            }
        }
    }
    float* out = (float*)d_out;

    const int C[4]   = {64, 128, 256, 512};
    const int N_[4]  = {1000, 1000, 1000, 1024};
    const int HW[4]  = {65536, 16384, 4096, 1024};
    const int OFF[4] = {0, 65536, 196608, 458752};
    const int TRI[4] = {1, 3, 10, 36};

    k_init<<<256, 256>>>();

    for (int lv = 0; lv < 4; lv++)
        k_gather<<<dim3(4, C[lv], 8), 256>>>(tf[lv], gf[lv], lv < 3 ? ix[lv] : nullptr,
                                             C[lv], N_[lv], HW[lv], OFF[lv]);
    for (int lv = 0; lv < 4; lv++)
        k_norms<<<dim3(8, 2, C[lv] / 64), 1024>>>(C[lv], OFF[lv], lv);
    for (int lv = 0; lv < 4; lv++)
        k_means<<<dim3(C[lv] / 8, 8, 2), 256>>>(C[lv], N_[lv], OFF[lv], lv);
    for (int lv = 0; lv < 4; lv++)
        k_style<<<dim3(8, 8, 8), 256>>>(C[lv], N_[lv], OFF[lv], lv);
    for (int lv = 0; lv < 4; lv++)
        k_cov<<<dim3(TRI[lv], 8), 256>>>(C[lv], N_[lv], OFF[lv], lv, C[lv] / 64);

    k_pairloss<<<32, 1024>>>();
    k_out<<<1, 32>>>(out);
}

// round 4
// speedup vs baseline: 3.1018x; 1.4656x over previous
#include <cuda_runtime.h>
#include <math.h>

// ---------------------------------------------------------------------------
// MotionOptimalTransportLoss — GB300 sm_103a
// tf32 mma.sync + cp.async double-buffered, launch-fused version.
// Levels: c in {64,128,256,512}, N = 1000 (lv 0-2) / 1024 (lv 3), NPAD=1024.
// Scratch: channel-major fp32 (c, NPAD) per (tensor, batch, level).
// ---------------------------------------------------------------------------

#define NPAD 1024
#define SCRPB 983040   // (64+128+256+512)*1024

__device__ float    g_scr[2u * 8u * SCRPB];
__device__ float    g_nsq[2 * 32 * 1024];
__device__ float    g_mu [2 * 32 * 512];
__device__ unsigned g_rmin[32 * 1024];
__device__ unsigned g_cmin[32 * 1024];
__device__ float    g_cov[32];
__device__ float    g_pl[32];

__constant__ int OFFC[4] = {0, 65536, 196608, 458752};

__device__ __forceinline__ unsigned f2o(float f) {
    unsigned u = __float_as_uint(f);
    return (u & 0x80000000u) ? ~u : (u | 0x80000000u);
}
__device__ __forceinline__ float o2f(unsigned u) {
    return __uint_as_float((u & 0x80000000u) ? (u ^ 0x80000000u) : ~u);
}
__device__ __forceinline__ void mma8(float* d, const unsigned* a, const unsigned* b) {
    asm volatile(
        "mma.sync.aligned.m16n8k8.row.col.f32.tf32.tf32.f32 "
        "{%0,%1,%2,%3}, {%4,%5,%6,%7}, {%8,%9}, {%0,%1,%2,%3};\n"
        : "+f"(d[0]), "+f"(d[1]), "+f"(d[2]), "+f"(d[3])
        : "r"(a[0]), "r"(a[1]), "r"(a[2]), "r"(a[3]), "r"(b[0]), "r"(b[1]));
}
__device__ __forceinline__ void cp16(float* dst, const float* src) {
    unsigned d = (unsigned)__cvta_generic_to_shared(dst);
    asm volatile("cp.async.cg.shared.global [%0], [%1], 16;\n" :: "r"(d), "l"(src));
}
__device__ __forceinline__ void cp_commit() { asm volatile("cp.async.commit_group;\n"); }
__device__ __forceinline__ void cp_wait1() { asm volatile("cp.async.wait_group 1;\n"); }
__device__ __forceinline__ void cp_wait0() { asm volatile("cp.async.wait_group 0;\n"); }

// ---------------------------------------------------------------------------
__global__ void k_init_a() {
    int i = blockIdx.x * blockDim.x + threadIdx.x;
    if (i < 32768) g_rmin[i] = 0xFF800000u;
}
__global__ void k_init_b() {
    int i = blockIdx.x * blockDim.x + threadIdx.x;
    if (i < 65536) g_nsq[i] = 0.f;
    if (i < 32768) g_cmin[i] = 0xFF800000u;
    if (i < 32) g_cov[i] = 0.f;
}

// ---------------------------------------------------------------------------
// gather (all levels): blocks/lv = 32*C -> offsets {0,2048,6144,14336}, tot 30720
// ---------------------------------------------------------------------------
__global__ void k_gather(const float* __restrict__ tf0, const float* __restrict__ gf0,
                         const float* __restrict__ tf1, const float* __restrict__ gf1,
                         const float* __restrict__ tf2, const float* __restrict__ gf2,
                         const float* __restrict__ tf3, const float* __restrict__ gf3,
                         const int* __restrict__ ix0, const int* __restrict__ ix1,
                         const int* __restrict__ ix2) {
    int bx = blockIdx.x;
    int lv, base;
    if (bx < 2048)       { lv = 0; base = 0; }
    else if (bx < 6144)  { lv = 1; base = 2048; }
    else if (bx < 14336) { lv = 2; base = 6144; }
    else                 { lv = 3; base = 14336; }
    int rem = bx - base;
    int C = 64 << lv;
    int nch = rem & 3;
    int ch = (rem >> 2) & (C - 1);
    int b = rem >> (2 + 6 + lv);
    int n = nch * 256 + threadIdx.x;

    const float* tgt; const float* gen; const int* idx;
    switch (lv) {
        case 0: tgt = tf0; gen = gf0; idx = ix0; break;
        case 1: tgt = tf1; gen = gf1; idx = ix1; break;
        case 2: tgt = tf2; gen = gf2; idx = ix2; break;
        default: tgt = tf3; gen = gf3; idx = 0; break;
    }
    int hw = 65536 >> (2 * lv);
    int N = (lv == 3) ? 1024 : 1000;

    float vx = 0.f, vy = 0.f;
    if (n < N) {
        int src = idx ? idx[b * 1000 + n] : n;
        size_t base2 = ((size_t)b * C + ch) * hw + src;
        vx = tgt[base2];
        vy = gen[base2];
    }
    size_t d = (size_t)b * SCRPB + OFFC[lv] + (size_t)ch * NPAD + n;
    g_scr[d] = vx;
    g_scr[(size_t)8 * SCRPB + d] = vy;
}

// ---------------------------------------------------------------------------
// stats: fused norms (atomicAdd partials over 64-ch slabs) + means (slab-owned)
// grid (15, 8, 2), block 1024. slabs per lv: 1,2,4,8.
// ---------------------------------------------------------------------------
__global__ void k_stats() {
    int s = blockIdx.x, lv = 0;
    while (s >= (1 << lv)) { s -= (1 << lv); lv++; }
    lv--;  // undo: decode below
    // redo decode cleanly
    s = blockIdx.x; lv = 0;
    { int cnt = 1; while (s >= cnt) { s -= cnt; lv++; cnt <<= 1; } }
    int cs = s * 64;
    int b = blockIdx.y, t = blockIdx.z;
    int tid = threadIdx.x;
    const float* base = g_scr + ((size_t)t * 8 + b) * SCRPB + OFFC[lv] + (size_t)cs * NPAD;

    // norms partial
    float acc = 0.f;
#pragma unroll 8
    for (int k = 0; k < 64; k++) { float v = base[(size_t)k * NPAD + tid]; acc += v * v; }
    atomicAdd(&g_nsq[(t * 32 + b * 4 + lv) * 1024 + tid], acc);

    // means: 32 warps x 2 channels each
    int w = tid >> 5, lane = tid & 31;
    float Nf = (lv == 3) ? 1024.f : 1000.f;
#pragma unroll
    for (int q = 0; q < 2; q++) {
        int chl = w + q * 32;
        const float* row = base + (size_t)chl * NPAD;
        float sum = 0.f;
        for (int n = lane; n < 1024; n += 32) sum += row[n];
#pragma unroll
        for (int o = 16; o; o >>= 1) sum += __shfl_xor_sync(0xFFFFFFFFu, sum, o);
        if (lane == 0) g_mu[(t * 32 + b * 4 + lv) * 512 + cs + chl] = sum / Nf;
    }
}

// ---------------------------------------------------------------------------
// cov (all levels): grid (50, 8). Two accumulators (Sx, Sy), cp.async 2-stage.
// CTA 64x64 channel tile, 8 warps of 32x16, smem [ch][k] stride 68, kc=64.
// ---------------------------------------------------------------------------
#define SC 68
#define CSTG (2 * 64 * SC)   // floats per stage (A + B tiles)
__global__ void __launch_bounds__(256, 2)
k_cov() {
    __shared__ float sm[2 * CSTG];
    __shared__ float red[256];

    // level + triangle decode
    int bx = blockIdx.x, lv = 0;
    { const int TRI[4] = {1, 3, 10, 36};
      while (bx >= TRI[lv]) { bx -= TRI[lv]; lv++; } }
    int T = (64 << lv) / 64;   // 1,2,4,8
    int ta = 0, rem = bx;
    while (rem >= T - ta) { rem -= (T - ta); ta++; }
    int tb = ta + rem;

    int c = 64 << lv;
    int off = OFFC[lv];
    int N = (lv == 3) ? 1024 : 1000;
    int b = blockIdx.y;
    int tid = threadIdx.x, wid = tid >> 5, lane = tid & 31;
    int g = lane >> 2, t = lane & 3;
    int wm = (wid >> 2) * 32, wn = (wid & 3) * 16;
    int cha0 = ta * 64, chb0 = tb * 64;
    const float* X = g_scr + (size_t)b * SCRPB + off;
    const float* Y = g_scr + (size_t)(8 + b) * SCRPB + off;

    float acc[2][2][2][4];
#pragma unroll
    for (int p = 0; p < 2; p++)
#pragma unroll
        for (int mt = 0; mt < 2; mt++)
#pragma unroll
            for (int nt = 0; nt < 2; nt++)
#pragma unroll
                for (int r = 0; r < 4; r++) acc[p][mt][nt][r] = 0.f;

    int lch = tid >> 2, lq = tid & 3;   // 64 rows x 4 loaders
    // iteration it = 0..31: p = it>>4 (X then Y), n0 = (it&15)*64
    auto np = 32;
    {
        // prologue: issue it=0
        const float* src = X;
        float* As = sm; float* Bs = sm + 64 * SC;
#pragma unroll
        for (int j = 0; j < 4; j++) {
            int col = lq * 16 + j * 4;
            cp16(&As[lch * SC + col], &src[(size_t)(cha0 + lch) * NPAD + col]);
            cp16(&Bs[lch * SC + col], &src[(size_t)(chb0 + lch) * NPAD + col]);
        }
        cp_commit();
    }
    for (int it = 0; it < np; it++) {
        if (it + 1 < np) {
            int p1 = (it + 1) >> 4, n1 = ((it + 1) & 15) * 64;
            const float* src = p1 ? Y : X;
            float* As = sm + ((it + 1) & 1) * CSTG;
            float* Bs = As + 64 * SC;
#pragma unroll
            for (int j = 0; j < 4; j++) {
                int col = lq * 16 + j * 4;
                cp16(&As[lch * SC + col], &src[(size_t)(cha0 + lch) * NPAD + n1 + col]);
                cp16(&Bs[lch * SC + col], &src[(size_t)(chb0 + lch) * NPAD + n1 + col]);
            }
            cp_commit();
            cp_wait1();
        } else cp_wait0();
        __syncthreads();

        int p = it >> 4;
        const float* As = sm + (it & 1) * CSTG;
        const float* Bs = As + 64 * SC;
#pragma unroll
        for (int k8 = 0; k8 < 8; k8++) {
            int kb = k8 * 8;
            unsigned a[2][4], bb[2][2];
#pragma unroll
            for (int mt = 0; mt < 2; mt++) {
                int r = wm + mt * 16 + g;
                a[mt][0] = __float_as_uint(As[r * SC + kb + t]);
                a[mt][1] = __float_as_uint(As[(r + 8) * SC + kb + t]);
                a[mt][2] = __float_as_uint(As[r * SC + kb + t + 4]);
                a[mt][3] = __float_as_uint(As[(r + 8) * SC + kb + t + 4]);
            }
#pragma unroll
            for (int nt = 0; nt < 2; nt++) {
                int cc = wn + nt * 8 + g;
                bb[nt][0] = __float_as_uint(Bs[cc * SC + kb + t]);
                bb[nt][1] = __float_as_uint(Bs[cc * SC + kb + t + 4]);
            }
#pragma unroll
            for (int mt = 0; mt < 2; mt++)
#pragma unroll
                for (int nt = 0; nt < 2; nt++) mma8(acc[p][mt][nt], a[mt], bb[nt]);
        }
        __syncthreads();
    }

    int pair = b * 4 + lv;
    const float* mux = g_mu + pair * 512;
    const float* muy = g_mu + (32 + pair) * 512;
    float Nf = (float)N, inv_nm1 = 1.f / (Nf - 1.f);
    float local = 0.f;
#pragma unroll
    for (int mt = 0; mt < 2; mt++)
#pragma unroll
        for (int h = 0; h < 2; h++) {
            int row = cha0 + wm + mt * 16 + g + h * 8;
            float mxa = mux[row], mya = muy[row];
#pragma unroll
            for (int nt = 0; nt < 2; nt++)
#pragma unroll
                for (int u = 0; u < 2; u++) {
                    int col = chb0 + wn + nt * 8 + 2 * t + u;
                    float cd = (acc[0][mt][nt][h * 2 + u] - acc[1][mt][nt][h * 2 + u]
                                - Nf * (mxa * mux[col] - mya * muy[col])) * inv_nm1;
                    float w = (ta == tb) ? ((col > row) ? 2.f : (col == row ? 1.f : 0.f)) : 2.f;
                    local += w * fabsf(cd);
                }
        }

    red[tid] = local;
    __syncthreads();
    for (int o = 128; o; o >>= 1) {
        if (tid < o) red[tid] += red[tid + o];
        __syncthreads();
    }
    if (tid == 0) atomicAdd(&g_cov[pair], red[0]);
}

// ---------------------------------------------------------------------------
// style (all levels): grid (256, 8); bx = lv*64 + tile (8x8 tiles of 128).
// cp.async 2-stage, smem [k][m] stride 136, 8 warps of 64x32.
// ---------------------------------------------------------------------------
#define SA 136
#define STG (32 * SA)
__global__ void __launch_bounds__(256, 2)
k_style() {
    __shared__ float sm[4 * STG];     // [stage][A,B]
    __shared__ unsigned rm[128], cm[128];

    int bx = blockIdx.x;
    int lv = bx >> 6, tile = bx & 63;
    int c = 64 << lv;
    int off = OFFC[lv];
    int N = (lv == 3) ? 1024 : 1000;
    int b = blockIdx.y;
    int i0 = (tile >> 3) * 128, j0 = (tile & 7) * 128;
    int tid = threadIdx.x, wid = tid >> 5, lane = tid & 31;
    int g = lane >> 2, t = lane & 3;
    int wm = (wid >> 2) * 64, wn = (wid & 3) * 32;
    const float* X = g_scr + (size_t)b * SCRPB + off;
    const float* Y = g_scr + (size_t)(8 + b) * SCRPB + off;

    if (tid < 128) { rm[tid] = 0xFF800000u; cm[tid] = 0xFF800000u; }

    float acc[4][4][4];
#pragma unroll
    for (int mt = 0; mt < 4; mt++)
#pragma unroll
        for (int nt = 0; nt < 4; nt++)
#pragma unroll
            for (int r = 0; r < 4; r++) acc[mt][nt][r] = 0.f;

    int lch = tid >> 3, lq = tid & 7;   // 32 rows x 8 loaders
    int nk = c / 32;
    {   // prologue: stage 0, k0 = 0
        float* As = sm; float* Bs = sm + STG;
#pragma unroll
        for (int j = 0; j < 4; j++) {
            int col = lq * 16 + j * 4;
            cp16(&As[lch * SA + col], &X[(size_t)lch * NPAD + i0 + col]);
            cp16(&Bs[lch * SA + col], &Y[(size_t)lch * NPAD + j0 + col]);
        }
        cp_commit();
    }
    for (int i = 0; i < nk; i++) {
        if (i + 1 < nk) {
            int k0 = (i + 1) * 32;
            float* As = sm + ((i + 1) & 1) * 2 * STG;
            float* Bs = As + STG;
#pragma unroll
            for (int j = 0; j < 4; j++) {
                int col = lq * 16 + j * 4;
                cp16(&As[lch * SA + col], &X[(size_t)(k0 + lch) * NPAD + i0 + col]);
                cp16(&Bs[lch * SA + col], &Y[(size_t)(k0 + lch) * NPAD + j0 + col]);
            }
            cp_commit();
            cp_wait1();
        } else cp_wait0();
        __syncthreads();

        const float* As = sm + (i & 1) * 2 * STG;
        const float* Bs = As + STG;
#pragma unroll
        for (int k8 = 0; k8 < 4; k8++) {
            int kb = k8 * 8;
            unsigned a[4][4], bb[4][2];
#pragma unroll
            for (int mt = 0; mt < 4; mt++) {
                int r = wm + mt * 16 + g;
                a[mt][0] = __float_as_uint(As[(kb + t) * SA + r]);
                a[mt][1] = __float_as_uint(As[(kb + t) * SA + r + 8]);
                a[mt][2] = __float_as_uint(As[(kb + t + 4) * SA + r]);
                a[mt][3] = __float_as_uint(As[(kb + t + 4) * SA + r + 8]);
            }
#pragma unroll
            for (int nt = 0; nt < 4; nt++) {
                int cc = wn + nt * 8 + g;
                bb[nt][0] = __float_as_uint(Bs[(kb + t) * SA + cc]);
                bb[nt][1] = __float_as_uint(Bs[(kb + t + 4) * SA + cc]);
            }
#pragma unroll
            for (int mt = 0; mt < 4; mt++)
#pragma unroll
                for (int nt = 0; nt < 4; nt++) mma8(acc[mt][nt], a[mt], bb[nt]);
        }
        __syncthreads();
    }

    // epilogue
    int pair = b * 4 + lv;
    const float* nsqX = g_nsq + pair * 1024;
    const float* nsqY = g_nsq + (32 + pair) * 1024;
    float invx[4][2], invy[4][2];
    bool vi[4][2], vj[4][2];
#pragma unroll
    for (int mt = 0; mt < 4; mt++)
#pragma unroll
        for (int h = 0; h < 2; h++) {
            int i = i0 + wm + mt * 16 + g + h * 8;
            vi[mt][h] = (i < N);
            invx[mt][h] = 1.f / (sqrtf(nsqX[i]) + 1e-10f);
        }
#pragma unroll
    for (int nt = 0; nt < 4; nt++)
#pragma unroll
        for (int u = 0; u < 2; u++) {
            int j = j0 + wn + nt * 8 + 2 * t + u;
            vj[nt][u] = (j < N);
            invy[nt][u] = 1.f / (sqrtf(nsqY[j]) + 1e-10f);
        }

    float rmin[4][2], cmin[4][2];
#pragma unroll
    for (int a1 = 0; a1 < 4; a1++)
#pragma unroll
        for (int a2 = 0; a2 < 2; a2++) { rmin[a1][a2] = INFINITY; cmin[a1][a2] = INFINITY; }

#pragma unroll
    for (int mt = 0; mt < 4; mt++)
#pragma unroll
        for (int nt = 0; nt < 4; nt++)
#pragma unroll
            for (int h = 0; h < 2; h++)
#pragma unroll
                for (int u = 0; u < 2; u++) {
                    float d = 1.f - acc[mt][nt][h * 2 + u] * invx[mt][h] * invy[nt][u];
                    float dr = vj[nt][u] ? d : INFINITY;
                    rmin[mt][h] = fminf(rmin[mt][h], dr);
                    float dc = vi[mt][h] ? d : INFINITY;
                    cmin[nt][u] = fminf(cmin[nt][u], dc);
                }

#pragma unroll
    for (int mt = 0; mt < 4; mt++)
#pragma unroll
        for (int h = 0; h < 2; h++) {
            float v = rmin[mt][h];
            v = fminf(v, __shfl_xor_sync(0xFFFFFFFFu, v, 1));
            v = fminf(v, __shfl_xor_sync(0xFFFFFFFFu, v, 2));
            rmin[mt][h] = v;
        }
#pragma unroll
    for (int nt = 0; nt < 4; nt++)
#pragma unroll
        for (int u = 0; u < 2; u++) {
            float v = cmin[nt][u];
            v = fminf(v, __shfl_xor_sync(0xFFFFFFFFu, v, 4));
            v = fminf(v, __shfl_xor_sync(0xFFFFFFFFu, v, 8));
            v = fminf(v, __shfl_xor_sync(0xFFFFFFFFu, v, 16));
            cmin[nt][u] = v;
        }
    if (t == 0) {
#pragma unroll
        for (int mt = 0; mt < 4; mt++)
#pragma unroll
            for (int h = 0; h < 2; h++)
                atomicMin(&rm[wm + mt * 16 + g + h * 8], f2o(rmin[mt][h]));
    }
    if (g == 0) {
#pragma unroll
        for (int nt = 0; nt < 4; nt++)
#pragma unroll
            for (int u = 0; u < 2; u++)
                atomicMin(&cm[wn + nt * 8 + 2 * t + u], f2o(cmin[nt][u]));
    }
    __syncthreads();
    if (tid < 128) {
        int i = i0 + tid; if (i < N) atomicMin(&g_rmin[pair * 1024 + i], rm[tid]);
        int j = j0 + tid; if (j < N) atomicMin(&g_cmin[pair * 1024 + j], cm[tid]);
    }
}

// ---------------------------------------------------------------------------
__device__ float blk_reduce1024(float v, float* smr) {
    int lane = threadIdx.x & 31, w = threadIdx.x >> 5;
#pragma unroll
    for (int o = 16; o; o >>= 1) v += __shfl_xor_sync(0xFFFFFFFFu, v, o);
    if (lane == 0) smr[w] = v;
    __syncthreads();
    float r = 0.f;
    if (w == 0) {
        r = smr[lane];
#pragma unroll
        for (int o = 16; o; o >>= 1) r += __shfl_xor_sync(0xFFFFFFFFu, r, o);
    }
    __syncthreads();
    return r;
}

__global__ void k_pairloss() {
    __shared__ float smr[32];
    const int cs[4] = {64, 128, 256, 512};
    int pair = blockIdx.x;
    int lv = pair & 3;
    int c = cs[lv], N = (lv == 3) ? 1024 : 1000;
    int tid = threadIdx.x;
    float v1 = 0.f, v2 = 0.f, v3 = 0.f;
    if (tid < N) {
        v1 = o2f(g_rmin[pair * 1024 + tid]);
        v2 = o2f(g_cmin[pair * 1024 + tid]);
    }
    if (tid < c) v3 = fabsf(g_mu[pair * 512 + tid] - g_mu[(32 + pair) * 512 + tid]);
    float s1 = blk_reduce1024(v1, smr);
    float s2 = blk_reduce1024(v2, smr);
    float s3 = blk_reduce1024(v3, smr);
    if (tid == 0) {
        float style = fmaxf(s1 / (float)N, s2 / (float)N);
        float mud   = s3 / (float)c;
        float cov   = g_cov[pair] / ((float)c * (float)c);
        g_pl[pair] = style + mud + cov;
    }
}

__global__ void k_out(float* __restrict__ out) {
    float v = g_pl[threadIdx.x];
#pragma unroll
    for (int o = 16; o; o >>= 1) v += __shfl_xor_sync(0xFFFFFFFFu, v, o);
    if (threadIdx.x == 0) out[0] = v / 8.f;
}

// ---------------------------------------------------------------------------
extern "C" void kernel_launch(void* const* d_in, const int* in_sizes, int n_in,
                              void* d_out, int out_size) {
    const float* tf[4] = {0, 0, 0, 0};
    const float* gf[4] = {0, 0, 0, 0};
    const int*   ix[3] = {0, 0, 0};

    const long long LSZ[4] = {8LL * 64 * 256 * 256, 8LL * 128 * 128 * 128,
                              8LL * 256 * 64 * 64,  8LL * 512 * 32 * 32};
    int n_idx = 0;
    for (int i = 0; i < n_in; i++) {
        long long sz = in_sizes[i];
        if (sz == 8LL * 1000) {
            if (n_idx < 3) ix[n_idx++] = (const int*)d_in[i];
            continue;
        }
        for (int lv = 0; lv < 4; lv++) {
            if (sz == LSZ[lv]) {
                if (!tf[lv]) tf[lv] = (const float*)d_in[i];
                else if (!gf[lv]) gf[lv] = (const float*)d_in[i];
                break;
            }
        }
    }
    float* out = (float*)d_out;

    k_init_a<<<128, 256>>>();
    k_init_b<<<256, 256>>>();
    k_gather<<<30720, 256>>>(tf[0], gf[0], tf[1], gf[1], tf[2], gf[2], tf[3], gf[3],
                             ix[0], ix[1], ix[2]);
    k_stats<<<dim3(15, 8, 2), 1024>>>();
    k_cov<<<dim3(50, 8), 256>>>();
    k_style<<<dim3(256, 8), 256>>>();
    k_pairloss<<<32, 1024>>>();
    k_out<<<1, 32>>>(out);
}

// round 6
// speedup vs baseline: 4.4661x; 1.4398x over previous
#include <cuda_runtime.h>
#include <cuda_fp16.h>
#include <math.h>

// ---------------------------------------------------------------------------
// MotionOptimalTransportLoss — GB300 sm_103a, fp16 mma.sync m16n8k16 version.
// Levels: c in {64,128,256,512}, N = 1000 (lv 0-2) / 1024 (lv 3), NPAD=1024.
// Scratch: TWO half copies: channel-major [c][1024] (cov) and point-major
// [1024][c] (style), per (tensor, batch, level).
// ---------------------------------------------------------------------------

#define NPAD 1024
#define SCRPB 983040   // elements per (tensor,batch): (64+128+256+512)*1024

__device__ __half    g_scm[2u * 8u * SCRPB];   // channel-major
__device__ __half    g_spm[2u * 8u * SCRPB];   // point-major
__device__ float     g_nsq[2 * 32 * 1024];
__device__ float     g_mu [2 * 32 * 512];
__device__ unsigned  g_rmin[32 * 1024];
__device__ unsigned  g_cmin[32 * 1024];
__device__ float     g_cov[32];
__device__ float     g_pl[32];

__constant__ int OFFC[4] = {0, 65536, 196608, 458752};

__device__ __forceinline__ unsigned f2o(float f) {
    unsigned u = __float_as_uint(f);
    return (u & 0x80000000u) ? ~u : (u | 0x80000000u);
}
__device__ __forceinline__ float o2f(unsigned u) {
    return __uint_as_float((u & 0x80000000u) ? (u ^ 0x80000000u) : ~u);
}
__device__ __forceinline__ void hmma16(float* d, const unsigned* a, const unsigned* b) {
    asm volatile(
        "mma.sync.aligned.m16n8k16.row.col.f32.f16.f16.f32 "
        "{%0,%1,%2,%3}, {%4,%5,%6,%7}, {%8,%9}, {%0,%1,%2,%3};\n"
        : "+f"(d[0]), "+f"(d[1]), "+f"(d[2]), "+f"(d[3])
        : "r"(a[0]), "r"(a[1]), "r"(a[2]), "r"(a[3]), "r"(b[0]), "r"(b[1]));
}
__device__ __forceinline__ void ldsm4(unsigned& r0, unsigned& r1, unsigned& r2,
                                      unsigned& r3, const void* p) {
    unsigned addr = (unsigned)__cvta_generic_to_shared(p);
    asm volatile("ldmatrix.sync.aligned.m8n8.x4.shared.b16 {%0,%1,%2,%3}, [%4];"
                 : "=r"(r0), "=r"(r1), "=r"(r2), "=r"(r3) : "r"(addr));
}
__device__ __forceinline__ void ldsm2(unsigned& r0, unsigned& r1, const void* p) {
    unsigned addr = (unsigned)__cvta_generic_to_shared(p);
    asm volatile("ldmatrix.sync.aligned.m8n8.x2.shared.b16 {%0,%1}, [%2];"
                 : "=r"(r0), "=r"(r1) : "r"(addr));
}
__device__ __forceinline__ void cp16(void* dst, const void* src) {
    unsigned d = (unsigned)__cvta_generic_to_shared(dst);
    asm volatile("cp.async.cg.shared.global [%0], [%1], 16;\n" :: "r"(d), "l"(src));
}
__device__ __forceinline__ void cp_commit() { asm volatile("cp.async.commit_group;\n"); }
__device__ __forceinline__ void cp_wait1()  { asm volatile("cp.async.wait_group 1;\n"); }
__device__ __forceinline__ void cp_wait0()  { asm volatile("cp.async.wait_group 0;\n"); }

// ---------------------------------------------------------------------------
__global__ void k_init() {
    int i = blockIdx.x * blockDim.x + threadIdx.x;
    if (i < 65536) g_nsq[i] = 0.f;
    if (i < 32768) { g_rmin[i] = 0xFF800000u; g_cmin[i] = 0xFF800000u; }
    if (i < 32) g_cov[i] = 0.f;
}

// ---------------------------------------------------------------------------
// gather (all levels) -> channel-major half scratch
// ---------------------------------------------------------------------------
__global__ void k_gather(const float* __restrict__ tf0, const float* __restrict__ gf0,
                         const float* __restrict__ tf1, const float* __restrict__ gf1,
                         const float* __restrict__ tf2, const float* __restrict__ gf2,
                         const float* __restrict__ tf3, const float* __restrict__ gf3,
                         const int* __restrict__ ix0, const int* __restrict__ ix1,
                         const int* __restrict__ ix2) {
    int bx = blockIdx.x;
    int lv, base;
    if (bx < 2048)       { lv = 0; base = 0; }
    else if (bx < 6144)  { lv = 1; base = 2048; }
    else if (bx < 14336) { lv = 2; base = 6144; }
    else                 { lv = 3; base = 14336; }
    int rem = bx - base;
    int C = 64 << lv;
    int nch = rem & 3;
    int ch = (rem >> 2) & (C - 1);
    int b = rem >> (2 + 6 + lv);
    int n = nch * 256 + threadIdx.x;

    const float* tgt; const float* gen; const int* idx;
    switch (lv) {
        case 0: tgt = tf0; gen = gf0; idx = ix0; break;
        case 1: tgt = tf1; gen = gf1; idx = ix1; break;
        case 2: tgt = tf2; gen = gf2; idx = ix2; break;
        default: tgt = tf3; gen = gf3; idx = 0; break;
    }
    int hw = 65536 >> (2 * lv);
    int N = (lv == 3) ? 1024 : 1000;

    float vx = 0.f, vy = 0.f;
    if (n < N) {
        int src = idx ? idx[b * 1000 + n] : n;
        size_t base2 = ((size_t)b * C + ch) * hw + src;
        vx = tgt[base2];
        vy = gen[base2];
    }
    size_t d = (size_t)b * SCRPB + OFFC[lv] + (size_t)ch * NPAD + n;
    g_scm[d] = __float2half_rn(vx);
    g_scm[(size_t)8 * SCRPB + d] = __float2half_rn(vy);
}

// ---------------------------------------------------------------------------
// transpose: channel-major [c][1024] -> point-major [1024][c], 64x64 half tiles
// grid 3840 (= 2 tensors * 8 batches * 240 tiles), block 256
// ---------------------------------------------------------------------------
__global__ void k_xpose() {
    int g = blockIdx.x;
    int tb = g / 240;
    int t2 = tb >> 3, b = tb & 7;
    int r = g % 240;
    int lv = 0;
    { const int sz[4] = {16, 32, 64, 128};
      while (r >= sz[lv]) { r -= sz[lv]; lv++; } }
    int c = 64 << lv;
    int ch0 = (r >> 4) * 64, n0 = (r & 15) * 64;
    const __half* src = g_scm + ((size_t)t2 * 8 + b) * SCRPB + OFFC[lv];
    __half* dst = g_spm + ((size_t)t2 * 8 + b) * SCRPB + OFFC[lv];

    __shared__ __half tl[64][72];
    int row = threadIdx.x >> 2, q = threadIdx.x & 3;
#pragma unroll
    for (int j = 0; j < 8; j++) {
        __half2 v = *(const __half2*)&src[(size_t)(ch0 + row) * NPAD + n0 + q * 16 + 2 * j];
        tl[row][q * 16 + 2 * j]     = __low2half(v);
        tl[row][q * 16 + 2 * j + 1] = __high2half(v);
    }
    __syncthreads();
#pragma unroll
    for (int j = 0; j < 8; j++) {
        int cc = q * 16 + 2 * j;
        __half2 w = __halves2half2(tl[cc][row], tl[cc + 1][row]);
        *(__half2*)&dst[(size_t)(n0 + row) * c + ch0 + cc] = w;
    }
}

// ---------------------------------------------------------------------------
// stats: norms partials (64-ch slabs, atomicAdd) + means, from half cm scratch
// grid (15, 8, 2), block 1024
// ---------------------------------------------------------------------------
__global__ void k_stats() {
    int s = blockIdx.x, lv = 0;
    { int cnt = 1; while (s >= cnt) { s -= cnt; lv++; cnt <<= 1; } }
    int cs = s * 64;
    int b = blockIdx.y, t = blockIdx.z;
    int tid = threadIdx.x;
    const __half* base = g_scm + ((size_t)t * 8 + b) * SCRPB + OFFC[lv] + (size_t)cs * NPAD;

    float acc = 0.f;
#pragma unroll 8
    for (int k = 0; k < 64; k++) {
        float v = __half2float(base[(size_t)k * NPAD + tid]);
        acc += v * v;
    }
    atomicAdd(&g_nsq[(t * 32 + b * 4 + lv) * 1024 + tid], acc);

    int w = tid >> 5, lane = tid & 31;
    float Nf = (lv == 3) ? 1024.f : 1000.f;
#pragma unroll
    for (int q = 0; q < 2; q++) {
        int chl = w + q * 32;
        const __half2* row2 = (const __half2*)(base + (size_t)chl * NPAD);
        float sum = 0.f;
        for (int n = lane; n < 512; n += 32) {
            float2 f = __half22float2(row2[n]);
            sum += f.x + f.y;
        }
#pragma unroll
        for (int o = 16; o; o >>= 1) sum += __shfl_xor_sync(0xFFFFFFFFu, sum, o);
        if (lane == 0) g_mu[(t * 32 + b * 4 + lv) * 512 + cs + chl] = sum / Nf;
    }
}

// ---------------------------------------------------------------------------
// cov: |X_cov - Y_cov| sums via fp16 mma from channel-major scratch.
// CTA 64x64 channel tile, 8 warps (2x4) of 32x16; smem [ch][n] stride 72,
// n-chunk 64 per stage, two-pass p (X then Y), cp.async double-buffered.
// ---------------------------------------------------------------------------
#define CS 72
__global__ void __launch_bounds__(256, 2)
k_cov() {
    __shared__ __align__(16) __half As[2][64 * CS];
    __shared__ __align__(16) __half Bsm[2][64 * CS];
    __shared__ float red[256];

    int bx = blockIdx.x, lv = 0;
    { const int TRI[4] = {1, 3, 10, 36};
      while (bx >= TRI[lv]) { bx -= TRI[lv]; lv++; } }
    int T = 1 << lv;
    int ta = 0, rem = bx;
    while (rem >= T - ta) { rem -= (T - ta); ta++; }
    int tb = ta + rem;

    int off = OFFC[lv];
    int N = (lv == 3) ? 1024 : 1000;
    int b = blockIdx.y;
    int tid = threadIdx.x, wid = tid >> 5, lane = tid & 31;
    int g = lane >> 2, t = lane & 3;
    int wm = (wid >> 2) * 32, wn = (wid & 3) * 16;
    int cha0 = ta * 64, chb0 = tb * 64;
    const __half* X = g_scm + (size_t)b * SCRPB + off;
    const __half* Y = g_scm + (size_t)(8 + b) * SCRPB + off;

    float acc[2][2][2][4];
#pragma unroll
    for (int p = 0; p < 2; p++)
#pragma unroll
        for (int mt = 0; mt < 2; mt++)
#pragma unroll
            for (int nt = 0; nt < 2; nt++)
#pragma unroll
                for (int r = 0; r < 4; r++) acc[p][mt][nt][r] = 0.f;

    int lrow = tid >> 2, lq = tid & 3;   // 64 rows x 4 loaders, 2 chunks each
    {   // prologue: stage it=0 (p=0, n0=0)
#pragma unroll
        for (int j = 0; j < 2; j++) {
            int col = lq * 16 + j * 8;
            cp16(&As[0][lrow * CS + col], &X[(size_t)(cha0 + lrow) * NPAD + col]);
            cp16(&Bsm[0][lrow * CS + col], &X[(size_t)(chb0 + lrow) * NPAD + col]);
        }
        cp_commit();
    }
    for (int it = 0; it < 32; it++) {
        if (it + 1 < 32) {
            int p1 = (it + 1) >> 4, n1 = ((it + 1) & 15) * 64;
            const __half* src = p1 ? Y : X;
            int nb = (it + 1) & 1;
#pragma unroll
            for (int j = 0; j < 2; j++) {
                int col = lq * 16 + j * 8;
                cp16(&As[nb][lrow * CS + col], &src[(size_t)(cha0 + lrow) * NPAD + n1 + col]);
                cp16(&Bsm[nb][lrow * CS + col], &src[(size_t)(chb0 + lrow) * NPAD + n1 + col]);
            }
            cp_commit();
            cp_wait1();
        } else cp_wait0();
        __syncthreads();

        int p = it >> 4, cb = it & 1;
#pragma unroll
        for (int k16 = 0; k16 < 64; k16 += 16) {
            unsigned a[2][4], bb[2][2];
#pragma unroll
            for (int mt = 0; mt < 2; mt++) {
                int ar = wm + mt * 16 + (lane & 15);
                ldsm4(a[mt][0], a[mt][1], a[mt][2], a[mt][3],
                      &As[cb][ar * CS + k16 + ((lane >> 4) << 3)]);
            }
#pragma unroll
            for (int nt = 0; nt < 2; nt++) {
                int br = wn + nt * 8 + (lane & 7);
                ldsm2(bb[nt][0], bb[nt][1],
                      &Bsm[cb][br * CS + k16 + (((lane >> 3) & 1) << 3)]);
            }
#pragma unroll
            for (int mt = 0; mt < 2; mt++)
#pragma unroll
                for (int nt = 0; nt < 2; nt++) hmma16(acc[p][mt][nt], a[mt], bb[nt]);
        }
        __syncthreads();
    }

    int pair = b * 4 + lv;
    const float* mux = g_mu + pair * 512;
    const float* muy = g_mu + (32 + pair) * 512;
    float Nf = (float)N, inv_nm1 = 1.f / (Nf - 1.f);
    float local = 0.f;
#pragma unroll
    for (int mt = 0; mt < 2; mt++)
#pragma unroll
        for (int h = 0; h < 2; h++) {
            int row = cha0 + wm + mt * 16 + g + h * 8;
            float mxa = mux[row], mya = muy[row];
#pragma unroll
            for (int nt = 0; nt < 2; nt++)
#pragma unroll
                for (int u = 0; u < 2; u++) {
                    int col = chb0 + wn + nt * 8 + 2 * t + u;
                    float cd = (acc[0][mt][nt][h * 2 + u] - acc[1][mt][nt][h * 2 + u]
                                - Nf * (mxa * mux[col] - mya * muy[col])) * inv_nm1;
                    float w = (ta == tb) ? ((col > row) ? 2.f : (col == row ? 1.f : 0.f)) : 2.f;
                    local += w * fabsf(cd);
                }
        }

    red[tid] = local;
    __syncthreads();
    for (int o = 128; o; o >>= 1) {
        if (tid < o) red[tid] += red[tid + o];
        __syncthreads();
    }
    if (tid == 0) atomicAdd(&g_cov[pair], red[0]);
}

// ---------------------------------------------------------------------------
// style: D = 1 - (X Y^T)/norms, fused row/col mins, fp16 mma from point-major.
// CTA 128x128 tile, 8 warps (2x4) of 64x32; smem [pt][ch] stride 40,
// K-stage 32 channels, cp.async double-buffered.
// grid (256, 8): bx = lv*64 + tile (8x8)
// ---------------------------------------------------------------------------
#define PS 40
__global__ void __launch_bounds__(256, 2)
k_style() {
    __shared__ __align__(16) __half As[2][128 * PS];
    __shared__ __align__(16) __half Bs[2][128 * PS];
    __shared__ unsigned rm[128], cmS[128];

    int bx = blockIdx.x;
    int lv = bx >> 6, tile = bx & 63;
    int c = 64 << lv;
    int off = OFFC[lv];
    int N = (lv == 3) ? 1024 : 1000;
    int b = blockIdx.y;
    int i0 = (tile >> 3) * 128, j0 = (tile & 7) * 128;
    int tid = threadIdx.x, wid = tid >> 5, lane = tid & 31;
    int g = lane >> 2, t = lane & 3;
    int wm = (wid >> 2) * 64, wn = (wid & 3) * 32;
    const __half* X = g_spm + (size_t)b * SCRPB + off;
    const __half* Y = g_spm + (size_t)(8 + b) * SCRPB + off;

    if (tid < 128) { rm[tid] = 0xFF800000u; cmS[tid] = 0xFF800000u; }

    float acc[4][4][4];
#pragma unroll
    for (int mt = 0; mt < 4; mt++)
#pragma unroll
        for (int nt = 0; nt < 4; nt++)
#pragma unroll
            for (int r = 0; r < 4; r++) acc[mt][nt][r] = 0.f;

    int lrow = tid >> 1, lq = tid & 1;   // 128 rows x 2 loaders, 2 chunks each
    int nk = c >> 5;
    {   // prologue: k0 = 0
#pragma unroll
        for (int j = 0; j < 2; j++) {
            int col = lq * 16 + j * 8;
            cp16(&As[0][lrow * PS + col], &X[(size_t)(i0 + lrow) * c + col]);
            cp16(&Bs[0][lrow * PS + col], &Y[(size_t)(j0 + lrow) * c + col]);
        }
        cp_commit();
    }
    for (int i = 0; i < nk; i++) {
        if (i + 1 < nk) {
            int k0 = (i + 1) * 32, nb = (i + 1) & 1;
#pragma unroll
            for (int j = 0; j < 2; j++) {
                int col = lq * 16 + j * 8;
                cp16(&As[nb][lrow * PS + col], &X[(size_t)(i0 + lrow) * c + k0 + col]);
                cp16(&Bs[nb][lrow * PS + col], &Y[(size_t)(j0 + lrow) * c + k0 + col]);
            }
            cp_commit();
            cp_wait1();
        } else cp_wait0();
        __syncthreads();

        int cb = i & 1;
#pragma unroll
        for (int kb = 0; kb < 32; kb += 16) {
            unsigned a[4][4], bb[4][2];
#pragma unroll
            for (int mt = 0; mt < 4; mt++) {
                int ar = wm + mt * 16 + (lane & 15);
                ldsm4(a[mt][0], a[mt][1], a[mt][2], a[mt][3],
                      &As[cb][ar * PS + kb + ((lane >> 4) << 3)]);
            }
#pragma unroll
            for (int nt = 0; nt < 4; nt++) {
                int br = wn + nt * 8 + (lane & 7);
                ldsm2(bb[nt][0], bb[nt][1],
                      &Bs[cb][br * PS + kb + (((lane >> 3) & 1) << 3)]);
            }
#pragma unroll
            for (int mt = 0; mt < 4; mt++)
#pragma unroll
                for (int nt = 0; nt < 4; nt++) hmma16(acc[mt][nt], a[mt], bb[nt]);
        }
        __syncthreads();
    }

    // epilogue
    int pair = b * 4 + lv;
    const float* nsqX = g_nsq + pair * 1024;
    const float* nsqY = g_nsq + (32 + pair) * 1024;
    float invx[4][2], invy[4][2];
    bool vi[4][2], vj[4][2];
#pragma unroll
    for (int mt = 0; mt < 4; mt++)
#pragma unroll
        for (int h = 0; h < 2; h++) {
            int i = i0 + wm + mt * 16 + g + h * 8;
            vi[mt][h] = (i < N);
            invx[mt][h] = 1.f / (sqrtf(nsqX[i]) + 1e-10f);
        }
#pragma unroll
    for (int nt = 0; nt < 4; nt++)
#pragma unroll
        for (int u = 0; u < 2; u++) {
            int j = j0 + wn + nt * 8 + 2 * t + u;
            vj[nt][u] = (j < N);
            invy[nt][u] = 1.f / (sqrtf(nsqY[j]) + 1e-10f);
        }

    float rmin[4][2], cmin[4][2];
#pragma unroll
    for (int a1 = 0; a1 < 4; a1++)
#pragma unroll
        for (int a2 = 0; a2 < 2; a2++) { rmin[a1][a2] = INFINITY; cmin[a1][a2] = INFINITY; }

#pragma unroll
    for (int mt = 0; mt < 4; mt++)
#pragma unroll
        for (int nt = 0; nt < 4; nt++)
#pragma unroll
            for (int h = 0; h < 2; h++)
#pragma unroll
                for (int u = 0; u < 2; u++) {
                    float d = 1.f - acc[mt][nt][h * 2 + u] * invx[mt][h] * invy[nt][u];
                    float dr = vj[nt][u] ? d : INFINITY;
                    rmin[mt][h] = fminf(rmin[mt][h], dr);
                    float dc = vi[mt][h] ? d : INFINITY;
                    cmin[nt][u] = fminf(cmin[nt][u], dc);
                }

#pragma unroll
    for (int mt = 0; mt < 4; mt++)
#pragma unroll
        for (int h = 0; h < 2; h++) {
            float v = rmin[mt][h];
            v = fminf(v, __shfl_xor_sync(0xFFFFFFFFu, v, 1));
            v = fminf(v, __shfl_xor_sync(0xFFFFFFFFu, v, 2));
            rmin[mt][h] = v;
        }
#pragma unroll
    for (int nt = 0; nt < 4; nt++)
#pragma unroll
        for (int u = 0; u < 2; u++) {
            float v = cmin[nt][u];
            v = fminf(v, __shfl_xor_sync(0xFFFFFFFFu, v, 4));
            v = fminf(v, __shfl_xor_sync(0xFFFFFFFFu, v, 8));
            v = fminf(v, __shfl_xor_sync(0xFFFFFFFFu, v, 16));
            cmin[nt][u] = v;
        }
    if (t == 0) {
#pragma unroll
        for (int mt = 0; mt < 4; mt++)
#pragma unroll
            for (int h = 0; h < 2; h++)
                atomicMin(&rm[wm + mt * 16 + g + h * 8], f2o(rmin[mt][h]));
    }
    if (g == 0) {
#pragma unroll
        for (int nt = 0; nt < 4; nt++)
#pragma unroll
            for (int u = 0; u < 2; u++)
                atomicMin(&cmS[wn + nt * 8 + 2 * t + u], f2o(cmin[nt][u]));
    }
    __syncthreads();
    if (tid < 128) {
        int i = i0 + tid; if (i < N) atomicMin(&g_rmin[pair * 1024 + i], rm[tid]);
        int j = j0 + tid; if (j < N) atomicMin(&g_cmin[pair * 1024 + j], cmS[tid]);
    }
}

// ---------------------------------------------------------------------------
__device__ float blk_reduce1024(float v, float* smr) {
    int lane = threadIdx.x & 31, w = threadIdx.x >> 5;
#pragma unroll
    for (int o = 16; o; o >>= 1) v += __shfl_xor_sync(0xFFFFFFFFu, v, o);
    if (lane == 0) smr[w] = v;
    __syncthreads();
    float r = 0.f;
    if (w == 0) {
        r = smr[lane];
#pragma unroll
        for (int o = 16; o; o >>= 1) r += __shfl_xor_sync(0xFFFFFFFFu, r, o);
    }
    __syncthreads();
    return r;
}

__global__ void k_pairloss() {
    __shared__ float smr[32];
    const int cs[4] = {64, 128, 256, 512};
    int pair = blockIdx.x;
    int lv = pair & 3;
    int c = cs[lv], N = (lv == 3) ? 1024 : 1000;
    int tid = threadIdx.x;
    float v1 = 0.f, v2 = 0.f, v3 = 0.f;
    if (tid < N) {
        v1 = o2f(g_rmin[pair * 1024 + tid]);
        v2 = o2f(g_cmin[pair * 1024 + tid]);
    }
    if (tid < c) v3 = fabsf(g_mu[pair * 512 + tid] - g_mu[(32 + pair) * 512 + tid]);
    float s1 = blk_reduce1024(v1, smr);
    float s2 = blk_reduce1024(v2, smr);
    float s3 = blk_reduce1024(v3, smr);
    if (tid == 0) {
        float style = fmaxf(s1 / (float)N, s2 / (float)N);
        float mud   = s3 / (float)c;
        float cov   = g_cov[pair] / ((float)c * (float)c);
        g_pl[pair] = style + mud + cov;
    }
}

__global__ void k_out(float* __restrict__ out) {
    float v = g_pl[threadIdx.x];
#pragma unroll
    for (int o = 16; o; o >>= 1) v += __shfl_xor_sync(0xFFFFFFFFu, v, o);
    if (threadIdx.x == 0) out[0] = v / 8.f;
}

// ---------------------------------------------------------------------------
extern "C" void kernel_launch(void* const* d_in, const int* in_sizes, int n_in,
                              void* d_out, int out_size) {
    const float* tf[4] = {0, 0, 0, 0};
    const float* gf[4] = {0, 0, 0, 0};
    const int*   ix[3] = {0, 0, 0};

    const long long LSZ[4] = {8LL * 64 * 256 * 256, 8LL * 128 * 128 * 128,
                              8LL * 256 * 64 * 64,  8LL * 512 * 32 * 32};
    int n_idx = 0;
    for (int i = 0; i < n_in; i++) {
        long long sz = in_sizes[i];
        if (sz == 8LL * 1000) {
            if (n_idx < 3) ix[n_idx++] = (const int*)d_in[i];
            continue;
        }
        for (int lv = 0; lv < 4; lv++) {
            if (sz == LSZ[lv]) {
                if (!tf[lv]) tf[lv] = (const float*)d_in[i];
                else if (!gf[lv]) gf[lv] = (const float*)d_in[i];
                break;
            }
        }
    }
    float* out = (float*)d_out;

    k_init<<<256, 256>>>();
    k_gather<<<30720, 256>>>(tf[0], gf[0], tf[1], gf[1], tf[2], gf[2], tf[3], gf[3],
                             ix[0], ix[1], ix[2]);
    k_xpose<<<3840, 256>>>();
    k_stats<<<dim3(15, 8, 2), 1024>>>();
    k_cov<<<dim3(50, 8), 256>>>();
    k_style<<<dim3(256, 8), 256>>>();
    k_pairloss<<<32, 1024>>>();
    k_out<<<1, 32>>>(out);
}

// round 7
// speedup vs baseline: 5.4399x; 1.2181x over previous
#include <cuda_runtime.h>
#include <cuda_fp16.h>
#include <math.h>

// ---------------------------------------------------------------------------
// MotionOptimalTransportLoss — GB300 sm_103a
// fp16 mma.sync m16n8k16; fused gather/transpose/stats; merged cov+style
// with 3-stage cp.async pipeline.
// Levels: c in {64,128,256,512}, N = 1000 (lv 0-2) / 1024 (lv 3), NPAD=1024.
// ---------------------------------------------------------------------------

#define NPAD 1024
#define SCRPB 983040   // (64+128+256+512)*1024

__device__ __half    g_scm[2u * 8u * SCRPB];   // channel-major [c][1024]
__device__ __half    g_spm[2u * 8u * SCRPB];   // point-major  [1024][c]
__device__ float     g_nsq[2 * 32 * 1024];     // squared-norm sums (fp32 source)
__device__ float     g_musum[2 * 32 * 512];    // per-channel SUMS (divide by N later)
__device__ unsigned  g_rmin[32 * 1024];
__device__ unsigned  g_cmin[32 * 1024];
__device__ float     g_cov[32];
__device__ float     g_pl[32];

__constant__ int OFFC[4] = {0, 65536, 196608, 458752};

__device__ __forceinline__ unsigned f2o(float f) {
    unsigned u = __float_as_uint(f);
    return (u & 0x80000000u) ? ~u : (u | 0x80000000u);
}
__device__ __forceinline__ float o2f(unsigned u) {
    return __uint_as_float((u & 0x80000000u) ? (u ^ 0x80000000u) : ~u);
}
__device__ __forceinline__ void hmma16(float* d, const unsigned* a, const unsigned* b) {
    asm volatile(
        "mma.sync.aligned.m16n8k16.row.col.f32.f16.f16.f32 "
        "{%0,%1,%2,%3}, {%4,%5,%6,%7}, {%8,%9}, {%0,%1,%2,%3};\n"
        : "+f"(d[0]), "+f"(d[1]), "+f"(d[2]), "+f"(d[3])
        : "r"(a[0]), "r"(a[1]), "r"(a[2]), "r"(a[3]), "r"(b[0]), "r"(b[1]));
}
__device__ __forceinline__ void ldsm4(unsigned& r0, unsigned& r1, unsigned& r2,
                                      unsigned& r3, const void* p) {
    unsigned addr = (unsigned)__cvta_generic_to_shared(p);
    asm volatile("ldmatrix.sync.aligned.m8n8.x4.shared.b16 {%0,%1,%2,%3}, [%4];"
                 : "=r"(r0), "=r"(r1), "=r"(r2), "=r"(r3) : "r"(addr));
}
__device__ __forceinline__ void ldsm2(unsigned& r0, unsigned& r1, const void* p) {
    unsigned addr = (unsigned)__cvta_generic_to_shared(p);
    asm volatile("ldmatrix.sync.aligned.m8n8.x2.shared.b16 {%0,%1}, [%2];"
                 : "=r"(r0), "=r"(r1) : "r"(addr));
}
__device__ __forceinline__ void cp16(void* dst, const void* src) {
    unsigned d = (unsigned)__cvta_generic_to_shared(dst);
    asm volatile("cp.async.cg.shared.global [%0], [%1], 16;\n" :: "r"(d), "l"(src));
}
__device__ __forceinline__ void cp_commit() { asm volatile("cp.async.commit_group;\n"); }
__device__ __forceinline__ void cp_wait1()  { asm volatile("cp.async.wait_group 1;\n"); }
__device__ __forceinline__ void cp_wait0()  { asm volatile("cp.async.wait_group 0;\n"); }

// ---------------------------------------------------------------------------
__global__ void k_init() {
    int i = blockIdx.x * blockDim.x + threadIdx.x;
    if (i < 65536) g_nsq[i] = 0.f;
    if (i < 32768) {
        g_rmin[i] = 0xFF800000u;
        g_cmin[i] = 0xFF800000u;
        g_musum[i] = 0.f;
    }
    if (i < 32) g_cov[i] = 0.f;
}

// ---------------------------------------------------------------------------
// gather2: fused gather + nsq (fp32) + channel sums + dual-layout write.
// Block = 64ch x 64n tile of one (tensor, batch, level). Grid 3840, block 256.
// ---------------------------------------------------------------------------
__global__ void k_gather2(const float* __restrict__ tf0, const float* __restrict__ gf0,
                          const float* __restrict__ tf1, const float* __restrict__ gf1,
                          const float* __restrict__ tf2, const float* __restrict__ gf2,
                          const float* __restrict__ tf3, const float* __restrict__ gf3,
                          const int* __restrict__ ix0, const int* __restrict__ ix1,
                          const int* __restrict__ ix2) {
    __shared__ __half tl[64][72];

    int gblk = blockIdx.x;
    int tb = gblk / 240;
    int t2 = tb >> 3, b = tb & 7;
    int r = gblk % 240;
    int lv = 0;
    { const int sz[4] = {16, 32, 64, 128};
      while (r >= sz[lv]) { r -= sz[lv]; lv++; } }
    int C = 64 << lv;
    int ch0 = (r >> 4) * 64, n0 = (r & 15) * 64;
    int hw = 65536 >> (2 * lv);
    int N = (lv == 3) ? 1024 : 1000;

    const float* feat; const int* idx;
    switch (lv) {
        case 0: feat = t2 ? gf0 : tf0; idx = ix0; break;
        case 1: feat = t2 ? gf1 : tf1; idx = ix1; break;
        case 2: feat = t2 ? gf2 : tf2; idx = ix2; break;
        default: feat = t2 ? gf3 : tf3; idx = 0; break;
    }

    int tid = threadIdx.x;
    int nl = tid & 63;                 // local n within tile
    int n = n0 + nl;                   // global point index
    int chg = tid >> 6;                // 0..3 channel group
    bool valid = (n < N);
    int src = 0;
    if (valid) src = idx ? idx[b * 1000 + n] : n;

    size_t fb = ((size_t)b * C + ch0) * hw + src;
    __half* cm = g_scm + ((size_t)t2 * 8 + b) * SCRPB + OFFC[lv];
    float nsq_loc = 0.f;
#pragma unroll
    for (int k = 0; k < 16; k++) {
        int chl = chg * 16 + k;
        float v = valid ? feat[fb + (size_t)chl * hw] : 0.f;
        nsq_loc += v * v;
        __half h = __float2half_rn(v);
        cm[(size_t)(ch0 + chl) * NPAD + n] = h;
        tl[chl][nl] = h;
    }
    int pairbase = (t2 * 32 + b * 4 + lv) * 1024;
    atomicAdd(&g_nsq[pairbase + n], nsq_loc);
    __syncthreads();

    // transposed write (point-major)
    __half* pm = g_spm + ((size_t)t2 * 8 + b) * SCRPB + OFFC[lv];
    int row = tid >> 2, q = tid & 3;
#pragma unroll
    for (int j = 0; j < 8; j++) {
        int cc = q * 16 + 2 * j;
        __half2 w = __halves2half2(tl[cc][row], tl[cc + 1][row]);
        *(__half2*)&pm[(size_t)(n0 + row) * C + ch0 + cc] = w;
    }

    // channel sums (means numerator)
    {
        int ch = tid >> 2;
        float s = 0.f;
#pragma unroll
        for (int i2 = 0; i2 < 16; i2++) s += __half2float(tl[ch][q * 16 + i2]);
        s += __shfl_xor_sync(0xFFFFFFFFu, s, 1);
        s += __shfl_xor_sync(0xFFFFFFFFu, s, 2);
        if (q == 0)
            atomicAdd(&g_musum[(t2 * 32 + b * 4 + lv) * 512 + ch0 + ch], s);
    }
}

// ---------------------------------------------------------------------------
// k_main: merged cov + style, 3-stage cp.async ring in dynamic smem.
// grid (306, 8): bx < 50 -> cov tile; else style (lv descending).
// ---------------------------------------------------------------------------
#define PS 40                 // style smem row stride (halves)
#define SSTGB (2 * 128 * PS * 2)   // 20480 B per style stage (A + B)
#define CS 72                 // cov smem row stride (halves)
#define CSTGB (2 * 64 * CS * 2)    // 18432 B per cov stage

extern __shared__ char dsm[];

__device__ __forceinline__ void cov_body(int bx, int b, unsigned* s_aux) {
    float* red = (float*)s_aux;
    int lv = 0;
    { const int TRI[4] = {1, 3, 10, 36};
      while (bx >= TRI[lv]) { bx -= TRI[lv]; lv++; } }
    int T = 1 << lv;
    int ta = 0, rem = bx;
    while (rem >= T - ta) { rem -= (T - ta); ta++; }
    int tb = ta + rem;

    int off = OFFC[lv];
    int N = (lv == 3) ? 1024 : 1000;
    int tid = threadIdx.x, wid = tid >> 5, lane = tid & 31;
    int g = lane >> 2, t = lane & 3;
    int wm = (wid >> 2) * 32, wn = (wid & 3) * 16;
    int cha0 = ta * 64, chb0 = tb * 64;
    const __half* X = g_scm + (size_t)b * SCRPB + off;
    const __half* Y = g_scm + (size_t)(8 + b) * SCRPB + off;

    float acc[2][2][2][4];
#pragma unroll
    for (int p = 0; p < 2; p++)
#pragma unroll
        for (int mt = 0; mt < 2; mt++)
#pragma unroll
            for (int nt = 0; nt < 2; nt++)
#pragma unroll
                for (int rr = 0; rr < 4; rr++) acc[p][mt][nt][rr] = 0.f;

    int lrow = tid >> 2, lq = tid & 3;

#define COV_ISSUE(IT) do {                                                     \
        int p_ = (IT) >> 4, n1_ = ((IT) & 15) * 64;                            \
        const __half* s_ = p_ ? Y : X;                                         \
        __half* A_ = (__half*)(dsm + ((IT) % 3) * CSTGB);                      \
        __half* B_ = A_ + 64 * CS;                                             \
        _Pragma("unroll")                                                      \
        for (int j = 0; j < 2; j++) {                                          \
            int col = lq * 16 + j * 8;                                         \
            cp16(&A_[lrow * CS + col], &s_[(size_t)(cha0 + lrow) * NPAD + n1_ + col]); \
            cp16(&B_[lrow * CS + col], &s_[(size_t)(chb0 + lrow) * NPAD + n1_ + col]); \
        }                                                                      \
        cp_commit();                                                           \
    } while (0)

    COV_ISSUE(0);
    COV_ISSUE(1);
    for (int it = 0; it < 32; it++) {
        if (it + 1 < 32) cp_wait1(); else cp_wait0();
        __syncthreads();
        if (it + 2 < 32) COV_ISSUE(it + 2);

        int p = it >> 4;
        const __half* As = (const __half*)(dsm + (it % 3) * CSTGB);
        const __half* Bsm = As + 64 * CS;
#pragma unroll
        for (int k16 = 0; k16 < 64; k16 += 16) {
            unsigned a[2][4], bb[2][2];
#pragma unroll
            for (int mt = 0; mt < 2; mt++) {
                int ar = wm + mt * 16 + (lane & 15);
                ldsm4(a[mt][0], a[mt][1], a[mt][2], a[mt][3],
                      &As[ar * CS + k16 + ((lane >> 4) << 3)]);
            }
#pragma unroll
            for (int nt = 0; nt < 2; nt++) {
                int br = wn + nt * 8 + (lane & 7);
                ldsm2(bb[nt][0], bb[nt][1],
                      &Bsm[br * CS + k16 + (((lane >> 3) & 1) << 3)]);
            }
#pragma unroll
            for (int mt = 0; mt < 2; mt++)
#pragma unroll
                for (int nt = 0; nt < 2; nt++) hmma16(acc[p][mt][nt], a[mt], bb[nt]);
        }
    }
#undef COV_ISSUE

    int pair = b * 4 + lv;
    const float* sux = g_musum + pair * 512;
    const float* suy = g_musum + (32 + pair) * 512;
    float Nf = (float)N, inv_nm1 = 1.f / (Nf - 1.f), invN = 1.f / Nf;
    float local = 0.f;
#pragma unroll
    for (int mt = 0; mt < 2; mt++)
#pragma unroll
        for (int h = 0; h < 2; h++) {
            int row = cha0 + wm + mt * 16 + g + h * 8;
            float sxa = sux[row], sya = suy[row];
#pragma unroll
            for (int nt = 0; nt < 2; nt++)
#pragma unroll
                for (int u = 0; u < 2; u++) {
                    int col = chb0 + wn + nt * 8 + 2 * t + u;
                    float corr = (sxa * sux[col] - sya * suy[col]) * invN;
                    float cd = (acc[0][mt][nt][h * 2 + u] - acc[1][mt][nt][h * 2 + u]
                                - corr) * inv_nm1;
                    float w = (ta == tb) ? ((col > row) ? 2.f : (col == row ? 1.f : 0.f)) : 2.f;
                    local += w * fabsf(cd);
                }
        }

    __syncthreads();
    red[tid] = local;
    __syncthreads();
    for (int o = 128; o; o >>= 1) {
        if (tid < o) red[tid] += red[tid + o];
        __syncthreads();
    }
    if (tid == 0) atomicAdd(&g_cov[pair], red[0]);
}

__device__ __forceinline__ void style_body(int sx, int b, unsigned* s_aux) {
    unsigned* rm = s_aux;          // [0..127]
    unsigned* cmS = s_aux + 128;   // [128..255]

    int lv = 3 - (sx >> 6);        // lv3 first (longest CTAs)
    int tile = sx & 63;
    int c = 64 << lv;
    int off = OFFC[lv];
    int N = (lv == 3) ? 1024 : 1000;
    int i0 = (tile >> 3) * 128, j0 = (tile & 7) * 128;
    int tid = threadIdx.x, wid = tid >> 5, lane = tid & 31;
    int g = lane >> 2, t = lane & 3;
    int wm = (wid >> 2) * 64, wn = (wid & 3) * 32;
    const __half* X = g_spm + (size_t)b * SCRPB + off;
    const __half* Y = g_spm + (size_t)(8 + b) * SCRPB + off;

    if (tid < 128) { rm[tid] = 0xFF800000u; cmS[tid] = 0xFF800000u; }

    float acc[4][4][4];
#pragma unroll
    for (int mt = 0; mt < 4; mt++)
#pragma unroll
        for (int nt = 0; nt < 4; nt++)
#pragma unroll
            for (int rr = 0; rr < 4; rr++) acc[mt][nt][rr] = 0.f;

    int lrow = tid >> 1, lq = tid & 1;
    int nk = c >> 5;

#define STY_ISSUE(ST) do {                                                     \
        int k0_ = (ST) * 32;                                                   \
        __half* A_ = (__half*)(dsm + ((ST) % 3) * SSTGB);                      \
        __half* B_ = A_ + 128 * PS;                                            \
        _Pragma("unroll")                                                      \
        for (int j = 0; j < 2; j++) {                                          \
            int col = lq * 16 + j * 8;                                         \
            cp16(&A_[lrow * PS + col], &X[(size_t)(i0 + lrow) * c + k0_ + col]); \
            cp16(&B_[lrow * PS + col], &Y[(size_t)(j0 + lrow) * c + k0_ + col]); \
        }                                                                      \
        cp_commit();                                                           \
    } while (0)

    STY_ISSUE(0);
    if (nk > 1) STY_ISSUE(1);
    for (int i = 0; i < nk; i++) {
        if (i + 1 < nk) cp_wait1(); else cp_wait0();
        __syncthreads();
        if (i + 2 < nk) STY_ISSUE(i + 2);

        const __half* As = (const __half*)(dsm + (i % 3) * SSTGB);
        const __half* Bs = As + 128 * PS;
#pragma unroll
        for (int kb = 0; kb < 32; kb += 16) {
            unsigned a[4][4], bb[4][2];
#pragma unroll
            for (int mt = 0; mt < 4; mt++) {
                int ar = wm + mt * 16 + (lane & 15);
                ldsm4(a[mt][0], a[mt][1], a[mt][2], a[mt][3],
                      &As[ar * PS + kb + ((lane >> 4) << 3)]);
            }
#pragma unroll
            for (int nt = 0; nt < 4; nt++) {
                int br = wn + nt * 8 + (lane & 7);
                ldsm2(bb[nt][0], bb[nt][1],
                      &Bs[br * PS + kb + (((lane >> 3) & 1) << 3)]);
            }
#pragma unroll
            for (int mt = 0; mt < 4; mt++)
#pragma unroll
                for (int nt = 0; nt < 4; nt++) hmma16(acc[mt][nt], a[mt], bb[nt]);
        }
    }
#undef STY_ISSUE

    // epilogue
    int pair = b * 4 + lv;
    const float* nsqX = g_nsq + pair * 1024;
    const float* nsqY = g_nsq + (32 + pair) * 1024;
    float invx[4][2], invy[4][2];
    bool vi[4][2], vj[4][2];
#pragma unroll
    for (int mt = 0; mt < 4; mt++)
#pragma unroll
        for (int h = 0; h < 2; h++) {
            int i = i0 + wm + mt * 16 + g + h * 8;
            vi[mt][h] = (i < N);
            invx[mt][h] = 1.f / (sqrtf(nsqX[i]) + 1e-10f);
        }
#pragma unroll
    for (int nt = 0; nt < 4; nt++)
#pragma unroll
        for (int u = 0; u < 2; u++) {
            int j = j0 + wn + nt * 8 + 2 * t + u;
            vj[nt][u] = (j < N);
            invy[nt][u] = 1.f / (sqrtf(nsqY[j]) + 1e-10f);
        }

    float rmin[4][2], cmin[4][2];
#pragma unroll
    for (int a1 = 0; a1 < 4; a1++)
#pragma unroll
        for (int a2 = 0; a2 < 2; a2++) { rmin[a1][a2] = INFINITY; cmin[a1][a2] = INFINITY; }

#pragma unroll
    for (int mt = 0; mt < 4; mt++)
#pragma unroll
        for (int nt = 0; nt < 4; nt++)
#pragma unroll
            for (int h = 0; h < 2; h++)
#pragma unroll
                for (int u = 0; u < 2; u++) {
                    float d = 1.f - acc[mt][nt][h * 2 + u] * invx[mt][h] * invy[nt][u];
                    float dr = vj[nt][u] ? d : INFINITY;
                    rmin[mt][h] = fminf(rmin[mt][h], dr);
                    float dc = vi[mt][h] ? d : INFINITY;
                    cmin[nt][u] = fminf(cmin[nt][u], dc);
                }

#pragma unroll
    for (int mt = 0; mt < 4; mt++)
#pragma unroll
        for (int h = 0; h < 2; h++) {
            float v = rmin[mt][h];
            v = fminf(v, __shfl_xor_sync(0xFFFFFFFFu, v, 1));
            v = fminf(v, __shfl_xor_sync(0xFFFFFFFFu, v, 2));
            rmin[mt][h] = v;
        }
#pragma unroll
    for (int nt = 0; nt < 4; nt++)
#pragma unroll
        for (int u = 0; u < 2; u++) {
            float v = cmin[nt][u];
            v = fminf(v, __shfl_xor_sync(0xFFFFFFFFu, v, 4));
            v = fminf(v, __shfl_xor_sync(0xFFFFFFFFu, v, 8));
            v = fminf(v, __shfl_xor_sync(0xFFFFFFFFu, v, 16));
            cmin[nt][u] = v;
        }
    if (t == 0) {
#pragma unroll
        for (int mt = 0; mt < 4; mt++)
#pragma unroll
            for (int h = 0; h < 2; h++)
                atomicMin(&rm[wm + mt * 16 + g + h * 8], f2o(rmin[mt][h]));
    }
    if (g == 0) {
#pragma unroll
        for (int nt = 0; nt < 4; nt++)
#pragma unroll
            for (int u = 0; u < 2; u++)
                atomicMin(&cmS[wn + nt * 8 + 2 * t + u], f2o(cmin[nt][u]));
    }
    __syncthreads();
    if (tid < 128) {
        int i = i0 + tid; if (i < N) atomicMin(&g_rmin[pair * 1024 + i], rm[tid]);
        int j = j0 + tid; if (j < N) atomicMin(&g_cmin[pair * 1024 + j], cmS[tid]);
    }
}

__global__ void __launch_bounds__(256, 2)
k_main() {
    __shared__ unsigned s_aux[256];
    if (blockIdx.x < 50) cov_body(blockIdx.x, blockIdx.y, s_aux);
    else                 style_body(blockIdx.x - 50, blockIdx.y, s_aux);
}

// ---------------------------------------------------------------------------
__device__ float blk_reduce1024(float v, float* smr) {
    int lane = threadIdx.x & 31, w = threadIdx.x >> 5;
#pragma unroll
    for (int o = 16; o; o >>= 1) v += __shfl_xor_sync(0xFFFFFFFFu, v, o);
    if (lane == 0) smr[w] = v;
    __syncthreads();
    float r = 0.f;
    if (w == 0) {
        r = smr[lane];
#pragma unroll
        for (int o = 16; o; o >>= 1) r += __shfl_xor_sync(0xFFFFFFFFu, r, o);
    }
    __syncthreads();
    return r;
}

__global__ void k_pairloss() {
    __shared__ float smr[32];
    const int cs[4] = {64, 128, 256, 512};
    int pair = blockIdx.x;
    int lv = pair & 3;
    int c = cs[lv], N = (lv == 3) ? 1024 : 1000;
    int tid = threadIdx.x;
    float v1 = 0.f, v2 = 0.f, v3 = 0.f;
    if (tid < N) {
        v1 = o2f(g_rmin[pair * 1024 + tid]);
        v2 = o2f(g_cmin[pair * 1024 + tid]);
    }
    if (tid < c) v3 = fabsf(g_musum[pair * 512 + tid] - g_musum[(32 + pair) * 512 + tid]);
    float s1 = blk_reduce1024(v1, smr);
    float s2 = blk_reduce1024(v2, smr);
    float s3 = blk_reduce1024(v3, smr);
    if (tid == 0) {
        float Nf = (float)N;
        float style = fmaxf(s1 / Nf, s2 / Nf);
        float mud   = s3 / ((float)c * Nf);       // sums -> means
        float cov   = g_cov[pair] / ((float)c * (float)c);
        g_pl[pair] = style + mud + cov;
    }
}

__global__ void k_out(float* __restrict__ out) {
    float v = g_pl[threadIdx.x];
#pragma unroll
    for (int o = 16; o; o >>= 1) v += __shfl_xor_sync(0xFFFFFFFFu, v, o);
    if (threadIdx.x == 0) out[0] = v / 8.f;
}

// ---------------------------------------------------------------------------
extern "C" void kernel_launch(void* const* d_in, const int* in_sizes, int n_in,
                              void* d_out, int out_size) {
    const float* tf[4] = {0, 0, 0, 0};
    const float* gf[4] = {0, 0, 0, 0};
    const int*   ix[3] = {0, 0, 0};

    const long long LSZ[4] = {8LL * 64 * 256 * 256, 8LL * 128 * 128 * 128,
                              8LL * 256 * 64 * 64,  8LL * 512 * 32 * 32};
    int n_idx = 0;
    for (int i = 0; i < n_in; i++) {
        long long sz = in_sizes[i];
        if (sz == 8LL * 1000) {
            if (n_idx < 3) ix[n_idx++] = (const int*)d_in[i];
            continue;
        }
        for (int lv = 0; lv < 4; lv++) {
            if (sz == LSZ[lv]) {
                if (!tf[lv]) tf[lv] = (const float*)d_in[i];
                else if (!gf[lv]) gf[lv] = (const float*)d_in[i];
                break;
            }
        }
    }
    float* out = (float*)d_out;

    const int DSM = 3 * SSTGB;   // 61440 B (>= 3 * CSTGB)
    cudaFuncSetAttribute(k_main, cudaFuncAttributeMaxDynamicSharedMemorySize, DSM);

    k_init<<<256, 256>>>();
    k_gather2<<<3840, 256>>>(tf[0], gf[0], tf[1], gf[1], tf[2], gf[2], tf[3], gf[3],
                             ix[0], ix[1], ix[2]);
    k_main<<<dim3(306, 8), 256, DSM>>>();
    k_pairloss<<<32, 1024>>>();
    k_out<<<1, 32>>>(out);
}

// round 8
// speedup vs baseline: 5.4897x; 1.0092x over previous
#include <cuda_runtime.h>
#include <cuda_fp16.h>
#include <math.h>

// ---------------------------------------------------------------------------
// MotionOptimalTransportLoss — GB300 sm_103a
// fp16 mma.sync m16n8k16; fused gather/transpose/stats; merged cov+style
// with 3-stage cp.async pipeline. B-fragments via ldmatrix.x4.
// Levels: c in {64,128,256,512}, N = 1000 (lv 0-2) / 1024 (lv 3), NPAD=1024.
// ---------------------------------------------------------------------------

#define NPAD 1024
#define SCRPB 983040   // (64+128+256+512)*1024

__device__ __half    g_scm[2u * 8u * SCRPB];   // channel-major [c][1024]
__device__ __half    g_spm[2u * 8u * SCRPB];   // point-major  [1024][c]
__device__ float     g_nsq[2 * 32 * 1024];     // squared-norm sums (fp32 source)
__device__ float     g_musum[2 * 32 * 512];    // per-channel SUMS
__device__ unsigned  g_rmin[32 * 1024];
__device__ unsigned  g_cmin[32 * 1024];
__device__ float     g_cov[32];
__device__ float     g_pl[32];

__constant__ int OFFC[4] = {0, 65536, 196608, 458752};

__device__ __forceinline__ unsigned f2o(float f) {
    unsigned u = __float_as_uint(f);
    return (u & 0x80000000u) ? ~u : (u | 0x80000000u);
}
__device__ __forceinline__ float o2f(unsigned u) {
    return __uint_as_float((u & 0x80000000u) ? (u ^ 0x80000000u) : ~u);
}
__device__ __forceinline__ void hmma16(float* d, const unsigned* a, const unsigned* b) {
    asm volatile(
        "mma.sync.aligned.m16n8k16.row.col.f32.f16.f16.f32 "
        "{%0,%1,%2,%3}, {%4,%5,%6,%7}, {%8,%9}, {%0,%1,%2,%3};\n"
        : "+f"(d[0]), "+f"(d[1]), "+f"(d[2]), "+f"(d[3])
        : "r"(a[0]), "r"(a[1]), "r"(a[2]), "r"(a[3]), "r"(b[0]), "r"(b[1]));
}
__device__ __forceinline__ void ldsm4(unsigned& r0, unsigned& r1, unsigned& r2,
                                      unsigned& r3, const void* p) {
    unsigned addr = (unsigned)__cvta_generic_to_shared(p);
    asm volatile("ldmatrix.sync.aligned.m8n8.x4.shared.b16 {%0,%1,%2,%3}, [%4];"
                 : "=r"(r0), "=r"(r1), "=r"(r2), "=r"(r3) : "r"(addr));
}
__device__ __forceinline__ void cp16(void* dst, const void* src) {
    unsigned d = (unsigned)__cvta_generic_to_shared(dst);
    asm volatile("cp.async.cg.shared.global [%0], [%1], 16;\n" :: "r"(d), "l"(src));
}
__device__ __forceinline__ void cp_commit() { asm volatile("cp.async.commit_group;\n"); }
__device__ __forceinline__ void cp_wait1()  { asm volatile("cp.async.wait_group 1;\n"); }
__device__ __forceinline__ void cp_wait0()  { asm volatile("cp.async.wait_group 0;\n"); }

// ---------------------------------------------------------------------------
__global__ void k_init_a() {
    int i = blockIdx.x * blockDim.x + threadIdx.x;
    if (i < 32768) { g_rmin[i] = 0xFF800000u; g_cmin[i] = 0xFF800000u; }
}
__global__ void k_init_b() {
    int i = blockIdx.x * blockDim.x + threadIdx.x;
    if (i < 65536) g_nsq[i] = 0.f;
    if (i < 32768) g_musum[i] = 0.f;
    if (i < 32) g_cov[i] = 0.f;
}

// ---------------------------------------------------------------------------
// gather2: fused gather + nsq (fp32) + channel sums + dual-layout write.
// Block = 64ch x 64n tile of one (tensor, batch, level). Grid 3840, block 256.
// ---------------------------------------------------------------------------
__global__ void k_gather2(const float* __restrict__ tf0, const float* __restrict__ gf0,
                          const float* __restrict__ tf1, const float* __restrict__ gf1,
                          const float* __restrict__ tf2, const float* __restrict__ gf2,
                          const float* __restrict__ tf3, const float* __restrict__ gf3,
                          const int* __restrict__ ix0, const int* __restrict__ ix1,
                          const int* __restrict__ ix2) {
    __shared__ __half tl[64][72];

    int gblk = blockIdx.x;
    int tb = gblk / 240;
    int t2 = tb >> 3, b = tb & 7;
    int r = gblk % 240;
    int lv = 0;
    { const int sz[4] = {16, 32, 64, 128};
      while (r >= sz[lv]) { r -= sz[lv]; lv++; } }
    int C = 64 << lv;
    int ch0 = (r >> 4) * 64, n0 = (r & 15) * 64;
    int hw = 65536 >> (2 * lv);
    int N = (lv == 3) ? 1024 : 1000;

    const float* feat; const int* idx;
    switch (lv) {
        case 0: feat = t2 ? gf0 : tf0; idx = ix0; break;
        case 1: feat = t2 ? gf1 : tf1; idx = ix1; break;
        case 2: feat = t2 ? gf2 : tf2; idx = ix2; break;
        default: feat = t2 ? gf3 : tf3; idx = 0; break;
    }

    int tid = threadIdx.x;
    int nl = tid & 63;
    int n = n0 + nl;
    int chg = tid >> 6;
    bool valid = (n < N);
    int src = 0;
    if (valid) src = idx ? idx[b * 1000 + n] : n;

    size_t fb = ((size_t)b * C + ch0) * hw + src;
    __half* cm = g_scm + ((size_t)t2 * 8 + b) * SCRPB + OFFC[lv];
    float nsq_loc = 0.f;
#pragma unroll
    for (int k = 0; k < 16; k++) {
        int chl = chg * 16 + k;
        float v = valid ? feat[fb + (size_t)chl * hw] : 0.f;
        nsq_loc += v * v;
        __half h = __float2half_rn(v);
        cm[(size_t)(ch0 + chl) * NPAD + n] = h;
        tl[chl][nl] = h;
    }
    int pairbase = (t2 * 32 + b * 4 + lv) * 1024;
    atomicAdd(&g_nsq[pairbase + n], nsq_loc);
    __syncthreads();

    __half* pm = g_spm + ((size_t)t2 * 8 + b) * SCRPB + OFFC[lv];
    int row = tid >> 2, q = tid & 3;
#pragma unroll
    for (int j = 0; j < 8; j++) {
        int cc = q * 16 + 2 * j;
        __half2 w = __halves2half2(tl[cc][row], tl[cc + 1][row]);
        *(__half2*)&pm[(size_t)(n0 + row) * C + ch0 + cc] = w;
    }

    {
        int ch = tid >> 2;
        float s = 0.f;
#pragma unroll
        for (int i2 = 0; i2 < 16; i2++) s += __half2float(tl[ch][q * 16 + i2]);
        s += __shfl_xor_sync(0xFFFFFFFFu, s, 1);
        s += __shfl_xor_sync(0xFFFFFFFFu, s, 2);
        if (q == 0)
            atomicAdd(&g_musum[(t2 * 32 + b * 4 + lv) * 512 + ch0 + ch], s);
    }
}

// ---------------------------------------------------------------------------
// k_main: merged cov + style, 3-stage cp.async ring in dynamic smem.
// grid (306, 8): bx < 50 -> cov tile; else style (lv descending).
// ---------------------------------------------------------------------------
#define PS 40                      // style smem row stride (halves)
#define SSTGB (2 * 128 * PS * 2)   // 20480 B per style stage (A + B)
#define CS 72                      // cov smem row stride (halves)
#define CSTGB (2 * 64 * CS * 2)    // 18432 B per cov stage

extern __shared__ char dsm[];

__device__ __forceinline__ void cov_body(int bx, int b, unsigned* s_aux) {
    float* red = (float*)s_aux;
    int lv = 0;
    { const int TRI[4] = {1, 3, 10, 36};
      while (bx >= TRI[lv]) { bx -= TRI[lv]; lv++; } }
    int T = 1 << lv;
    int ta = 0, rem = bx;
    while (rem >= T - ta) { rem -= (T - ta); ta++; }
    int tb = ta + rem;

    int off = OFFC[lv];
    int N = (lv == 3) ? 1024 : 1000;
    int tid = threadIdx.x, wid = tid >> 5, lane = tid & 31;
    int g = lane >> 2, t = lane & 3;
    int grp = lane >> 3;               // 0..3 (ldmatrix address group)
    int wm = (wid >> 2) * 32, wn = (wid & 3) * 16;
    int cha0 = ta * 64, chb0 = tb * 64;
    const __half* X = g_scm + (size_t)b * SCRPB + off;
    const __half* Y = g_scm + (size_t)(8 + b) * SCRPB + off;

    float acc[2][2][2][4];
#pragma unroll
    for (int p = 0; p < 2; p++)
#pragma unroll
        for (int mt = 0; mt < 2; mt++)
#pragma unroll
            for (int nt = 0; nt < 2; nt++)
#pragma unroll
                for (int rr = 0; rr < 4; rr++) acc[p][mt][nt][rr] = 0.f;

    int lrow = tid >> 2, lq = tid & 3;

#define COV_ISSUE(IT) do {                                                     \
        int p_ = (IT) >> 4, n1_ = ((IT) & 15) * 64;                            \
        const __half* s_ = p_ ? Y : X;                                         \
        __half* A_ = (__half*)(dsm + ((IT) % 3) * CSTGB);                      \
        __half* B_ = A_ + 64 * CS;                                             \
        _Pragma("unroll")                                                      \
        for (int j = 0; j < 2; j++) {                                          \
            int col = lq * 16 + j * 8;                                         \
            cp16(&A_[lrow * CS + col], &s_[(size_t)(cha0 + lrow) * NPAD + n1_ + col]); \
            cp16(&B_[lrow * CS + col], &s_[(size_t)(chb0 + lrow) * NPAD + n1_ + col]); \
        }                                                                      \
        cp_commit();                                                           \
    } while (0)

    COV_ISSUE(0);
    COV_ISSUE(1);
    for (int it = 0; it < 32; it++) {
        if (it + 1 < 32) cp_wait1(); else cp_wait0();
        __syncthreads();
        if (it + 2 < 32) COV_ISSUE(it + 2);

        int p = it >> 4;
        const __half* As = (const __half*)(dsm + (it % 3) * CSTGB);
        const __half* Bsm = As + 64 * CS;
#pragma unroll
        for (int k16 = 0; k16 < 64; k16 += 16) {
            unsigned a[2][4], bb[2][2];
#pragma unroll
            for (int mt = 0; mt < 2; mt++) {
                int ar = wm + mt * 16 + (lane & 15);
                ldsm4(a[mt][0], a[mt][1], a[mt][2], a[mt][3],
                      &As[ar * CS + k16 + ((lane >> 4) << 3)]);
            }
            {   // B: both nt in one ldmatrix.x4
                int br = wn + (grp >> 1) * 8 + (lane & 7);
                ldsm4(bb[0][0], bb[0][1], bb[1][0], bb[1][1],
                      &Bsm[br * CS + k16 + ((grp & 1) << 3)]);
            }
#pragma unroll
            for (int mt = 0; mt < 2; mt++)
#pragma unroll
                for (int nt = 0; nt < 2; nt++) hmma16(acc[p][mt][nt], a[mt], bb[nt]);
        }
    }
#undef COV_ISSUE

    int pair = b * 4 + lv;
    const float* sux = g_musum + pair * 512;
    const float* suy = g_musum + (32 + pair) * 512;
    float Nf = (float)N, inv_nm1 = 1.f / (Nf - 1.f), invN = 1.f / Nf;
    float local = 0.f;
#pragma unroll
    for (int mt = 0; mt < 2; mt++)
#pragma unroll
        for (int h = 0; h < 2; h++) {
            int row = cha0 + wm + mt * 16 + g + h * 8;
            float sxa = sux[row], sya = suy[row];
#pragma unroll
            for (int nt = 0; nt < 2; nt++)
#pragma unroll
                for (int u = 0; u < 2; u++) {
                    int col = chb0 + wn + nt * 8 + 2 * t + u;
                    float corr = (sxa * sux[col] - sya * suy[col]) * invN;
                    float cd = (acc[0][mt][nt][h * 2 + u] - acc[1][mt][nt][h * 2 + u]
                                - corr) * inv_nm1;
                    float w = (ta == tb) ? ((col > row) ? 2.f : (col == row ? 1.f : 0.f)) : 2.f;
                    local += w * fabsf(cd);
                }
        }

    __syncthreads();
    red[tid] = local;
    __syncthreads();
    for (int o = 128; o; o >>= 1) {
        if (tid < o) red[tid] += red[tid + o];
        __syncthreads();
    }
    if (tid == 0) atomicAdd(&g_cov[pair], red[0]);
}

__device__ __forceinline__ void style_body(int sx, int b, unsigned* s_aux) {
    unsigned* rm = s_aux;
    unsigned* cmS = s_aux + 128;

    int lv = 3 - (sx >> 6);
    int tile = sx & 63;
    int c = 64 << lv;
    int off = OFFC[lv];
    int N = (lv == 3) ? 1024 : 1000;
    int i0 = (tile >> 3) * 128, j0 = (tile & 7) * 128;
    int tid = threadIdx.x, wid = tid >> 5, lane = tid & 31;
    int g = lane >> 2, t = lane & 3;
    int grp = lane >> 3;
    int wm = (wid >> 2) * 64, wn = (wid & 3) * 32;
    const __half* X = g_spm + (size_t)b * SCRPB + off;
    const __half* Y = g_spm + (size_t)(8 + b) * SCRPB + off;

    if (tid < 128) { rm[tid] = 0xFF800000u; cmS[tid] = 0xFF800000u; }

    float acc[4][4][4];
#pragma unroll
    for (int mt = 0; mt < 4; mt++)
#pragma unroll
        for (int nt = 0; nt < 4; nt++)
#pragma unroll
            for (int rr = 0; rr < 4; rr++) acc[mt][nt][rr] = 0.f;

    int lrow = tid >> 1, lq = tid & 1;
    int nk = c >> 5;

#define STY_ISSUE(ST) do {                                                     \
        int k0_ = (ST) * 32;                                                   \
        __half* A_ = (__half*)(dsm + ((ST) % 3) * SSTGB);                      \
        __half* B_ = A_ + 128 * PS;                                            \
        _Pragma("unroll")                                                      \
        for (int j = 0; j < 2; j++) {                                          \
            int col = lq * 16 + j * 8;                                         \
            cp16(&A_[lrow * PS + col], &X[(size_t)(i0 + lrow) * c + k0_ + col]); \
            cp16(&B_[lrow * PS + col], &Y[(size_t)(j0 + lrow) * c + k0_ + col]); \
        }                                                                      \
        cp_commit();                                                           \
    } while (0)

    STY_ISSUE(0);
    if (nk > 1) STY_ISSUE(1);
    for (int i = 0; i < nk; i++) {
        if (i + 1 < nk) cp_wait1(); else cp_wait0();
        __syncthreads();
        if (i + 2 < nk) STY_ISSUE(i + 2);

        const __half* As = (const __half*)(dsm + (i % 3) * SSTGB);
        const __half* Bs = As + 128 * PS;
#pragma unroll
        for (int kb = 0; kb < 32; kb += 16) {
            unsigned a[4][4], bb[4][2];
#pragma unroll
            for (int mt = 0; mt < 4; mt++) {
                int ar = wm + mt * 16 + (lane & 15);
                ldsm4(a[mt][0], a[mt][1], a[mt][2], a[mt][3],
                      &As[ar * PS + kb + ((lane >> 4) << 3)]);
            }
#pragma unroll
            for (int pp = 0; pp < 2; pp++) {   // nt pairs {0,1}, {2,3}
                int br = wn + (2 * pp + (grp >> 1)) * 8 + (lane & 7);
                ldsm4(bb[2 * pp][0], bb[2 * pp][1], bb[2 * pp + 1][0], bb[2 * pp + 1][1],
                      &Bs[br * PS + kb + ((grp & 1) << 3)]);
            }
#pragma unroll
            for (int mt = 0; mt < 4; mt++)
#pragma unroll
                for (int nt = 0; nt < 4; nt++) hmma16(acc[mt][nt], a[mt], bb[nt]);
        }
    }
#undef STY_ISSUE

    int pair = b * 4 + lv;
    const float* nsqX = g_nsq + pair * 1024;
    const float* nsqY = g_nsq + (32 + pair) * 1024;
    float invx[4][2], invy[4][2];
    bool vi[4][2], vj[4][2];
#pragma unroll
    for (int mt = 0; mt < 4; mt++)
#pragma unroll
        for (int h = 0; h < 2; h++) {
            int i = i0 + wm + mt * 16 + g + h * 8;
            vi[mt][h] = (i < N);
            invx[mt][h] = 1.f / (sqrtf(nsqX[i]) + 1e-10f);
        }
#pragma unroll
    for (int nt = 0; nt < 4; nt++)
#pragma unroll
        for (int u = 0; u < 2; u++) {
            int j = j0 + wn + nt * 8 + 2 * t + u;
            vj[nt][u] = (j < N);
            invy[nt][u] = 1.f / (sqrtf(nsqY[j]) + 1e-10f);
        }

    float rmin[4][2], cmin[4][2];
#pragma unroll
    for (int a1 = 0; a1 < 4; a1++)
#pragma unroll
        for (int a2 = 0; a2 < 2; a2++) { rmin[a1][a2] = INFINITY; cmin[a1][a2] = INFINITY; }

#pragma unroll
    for (int mt = 0; mt < 4; mt++)
#pragma unroll
        for (int nt = 0; nt < 4; nt++)
#pragma unroll
            for (int h = 0; h < 2; h++)
#pragma unroll
                for (int u = 0; u < 2; u++) {
                    float d = 1.f - acc[mt][nt][h * 2 + u] * invx[mt][h] * invy[nt][u];
                    float dr = vj[nt][u] ? d : INFINITY;
                    rmin[mt][h] = fminf(rmin[mt][h], dr);
                    float dc = vi[mt][h] ? d : INFINITY;
                    cmin[nt][u] = fminf(cmin[nt][u], dc);
                }

#pragma unroll
    for (int mt = 0; mt < 4; mt++)
#pragma unroll
        for (int h = 0; h < 2; h++) {
            float v = rmin[mt][h];
            v = fminf(v, __shfl_xor_sync(0xFFFFFFFFu, v, 1));
            v = fminf(v, __shfl_xor_sync(0xFFFFFFFFu, v, 2));
            rmin[mt][h] = v;
        }
#pragma unroll
    for (int nt = 0; nt < 4; nt++)
#pragma unroll
        for (int u = 0; u < 2; u++) {
            float v = cmin[nt][u];
            v = fminf(v, __shfl_xor_sync(0xFFFFFFFFu, v, 4));
            v = fminf(v, __shfl_xor_sync(0xFFFFFFFFu, v, 8));
            v = fminf(v, __shfl_xor_sync(0xFFFFFFFFu, v, 16));
            cmin[nt][u] = v;
        }
    if (t == 0) {
#pragma unroll
        for (int mt = 0; mt < 4; mt++)
#pragma unroll
            for (int h = 0; h < 2; h++)
                atomicMin(&rm[wm + mt * 16 + g + h * 8], f2o(rmin[mt][h]));
    }
    if (g == 0) {
#pragma unroll
        for (int nt = 0; nt < 4; nt++)
#pragma unroll
            for (int u = 0; u < 2; u++)
                atomicMin(&cmS[wn + nt * 8 + 2 * t + u], f2o(cmin[nt][u]));
    }
    __syncthreads();
    if (tid < 128) {
        int i = i0 + tid; if (i < N) atomicMin(&g_rmin[pair * 1024 + i], rm[tid]);
        int j = j0 + tid; if (j < N) atomicMin(&g_cmin[pair * 1024 + j], cmS[tid]);
    }
}

__global__ void __launch_bounds__(256, 2)
k_main() {
    __shared__ unsigned s_aux[256];
    if (blockIdx.x < 50) cov_body(blockIdx.x, blockIdx.y, s_aux);
    else                 style_body(blockIdx.x - 50, blockIdx.y, s_aux);
}

// ---------------------------------------------------------------------------
__device__ float blk_reduce1024(float v, float* smr) {
    int lane = threadIdx.x & 31, w = threadIdx.x >> 5;
#pragma unroll
    for (int o = 16; o; o >>= 1) v += __shfl_xor_sync(0xFFFFFFFFu, v, o);
    if (lane == 0) smr[w] = v;
    __syncthreads();
    float r = 0.f;
    if (w == 0) {
        r = smr[lane];
#pragma unroll
        for (int o = 16; o; o >>= 1) r += __shfl_xor_sync(0xFFFFFFFFu, r, o);
    }
    __syncthreads();
    return r;
}

__global__ void k_pairloss() {
    __shared__ float smr[32];
    const int cs[4] = {64, 128, 256, 512};
    int pair = blockIdx.x;
    int lv = pair & 3;
    int c = cs[lv], N = (lv == 3) ? 1024 : 1000;
    int tid = threadIdx.x;
    float v1 = 0.f, v2 = 0.f, v3 = 0.f;
    if (tid < N) {
        v1 = o2f(g_rmin[pair * 1024 + tid]);
        v2 = o2f(g_cmin[pair * 1024 + tid]);
    }
    if (tid < c) v3 = fabsf(g_musum[pair * 512 + tid] - g_musum[(32 + pair) * 512 + tid]);
    float s1 = blk_reduce1024(v1, smr);
    float s2 = blk_reduce1024(v2, smr);
    float s3 = blk_reduce1024(v3, smr);
    if (tid == 0) {
        float Nf = (float)N;
        float style = fmaxf(s1 / Nf, s2 / Nf);
        float mud   = s3 / ((float)c * Nf);
        float cov   = g_cov[pair] / ((float)c * (float)c);
        g_pl[pair] = style + mud + cov;
    }
}

__global__ void k_out(float* __restrict__ out) {
    float v = g_pl[threadIdx.x];
#pragma unroll
    for (int o = 16; o; o >>= 1) v += __shfl_xor_sync(0xFFFFFFFFu, v, o);
    if (threadIdx.x == 0) out[0] = v / 8.f;
}

// ---------------------------------------------------------------------------
extern "C" void kernel_launch(void* const* d_in, const int* in_sizes, int n_in,
                              void* d_out, int out_size) {
    const float* tf[4] = {0, 0, 0, 0};
    const float* gf[4] = {0, 0, 0, 0};
    const int*   ix[3] = {0, 0, 0};

    const long long LSZ[4] = {8LL * 64 * 256 * 256, 8LL * 128 * 128 * 128,
                              8LL * 256 * 64 * 64,  8LL * 512 * 32 * 32};
    int n_idx = 0;
    for (int i = 0; i < n_in; i++) {
        long long sz = in_sizes[i];
        if (sz == 8LL * 1000) {
            if (n_idx < 3) ix[n_idx++] = (const int*)d_in[i];
            continue;
        }
        for (int lv = 0; lv < 4; lv++) {
            if (sz == LSZ[lv]) {
                if (!tf[lv]) tf[lv] = (const float*)d_in[i];
                else if (!gf[lv]) gf[lv] = (const float*)d_in[i];
                break;
            }
        }
    }
    float* out = (float*)d_out;

    const int DSM = 3 * SSTGB;   // 61440 B (>= 3 * CSTGB)
    cudaFuncSetAttribute(k_main, cudaFuncAttributeMaxDynamicSharedMemorySize, DSM);

    // k_main is deliberately the 4th launch: the ncu window captures launch #4.
    k_init_a<<<128, 256>>>();
    k_init_b<<<256, 256>>>();
    k_gather2<<<3840, 256>>>(tf[0], gf[0], tf[1], gf[1], tf[2], gf[2], tf[3], gf[3],
                             ix[0], ix[1], ix[2]);
    k_main<<<dim3(306, 8), 256, DSM>>>();
    k_pairloss<<<32, 1024>>>();
    k_out<<<1, 32>>>(out);
}